// round 1
// baseline (speedup 1.0000x reference)
#include <cuda_runtime.h>
#include <cuda_bf16.h>
#include <math.h>

// ---------------------------------------------------------------------------
// Problem constants
// ---------------------------------------------------------------------------
#define BB 4
#define NN 16384
#define CC 128
#define MM 1024
#define KK 32
#define RROWS (BB*MM*KK)        // 131072
#define KPAD1 136               // 131 padded to multiple of 8
#define COUT1 128
#define COUT2 128
#define COUT3 256
#define STAT_ROWS 512
#define STAT_BLOCKS (RROWS/STAT_ROWS)   // 256
#define OUT_XYZ_ELEMS (BB*MM*3)         // 12288

// ---------------------------------------------------------------------------
// Scratch (static device globals -- no allocation APIs allowed)
// ---------------------------------------------------------------------------
__device__ float g_featT[(size_t)BB*NN*CC];       // 32 MB   (B,N,C)
__device__ int   g_idx[(size_t)BB*MM*KK];         // 512 KB
__device__ float g_X1[(size_t)RROWS*KPAD1];       // 71 MB
__device__ float g_Y1[(size_t)RROWS*COUT1];       // 64 MB
__device__ float g_Y2[(size_t)RROWS*COUT2];       // 64 MB
__device__ float g_Y3[(size_t)RROWS*COUT3];       // 128 MB
__device__ float g_w1p[COUT1*KPAD1];
__device__ float g_part[STAT_BLOCKS*2*COUT3];     // stats partials
__device__ float g_bn[6*COUT3];                   // a1,c1,a2,c2,a3,c3

// ---------------------------------------------------------------------------
// 1) transpose features (B,C,N) -> (B,N,C)
// ---------------------------------------------------------------------------
__global__ void transpose_feat_kernel(const float* __restrict__ f) {
    __shared__ float tile[32][33];
    int b  = blockIdx.z;
    int n0 = blockIdx.x * 32;
    int c0 = blockIdx.y * 32;
    int tx = threadIdx.x, ty = threadIdx.y;
    tile[ty][tx] = f[((size_t)b*CC + (c0+ty))*NN + (n0+tx)];
    __syncthreads();
    g_featT[((size_t)b*NN + (n0+ty))*CC + (c0+tx)] = tile[tx][ty];
}

// ---------------------------------------------------------------------------
// 2) ball query: warp per query. Writes new_xyz directly into d_out[0:12288)
// ---------------------------------------------------------------------------
__global__ void ballquery_kernel(const float* __restrict__ xyz,
                                 const int*   __restrict__ indices,
                                 float*       __restrict__ out_newxyz) {
    int gw   = (blockIdx.x * blockDim.x + threadIdx.x) >> 5;
    int lane = threadIdx.x & 31;
    if (gw >= BB*MM) return;
    int b = gw >> 10;                 // MM = 1024
    const float R2 = (float)(0.4 * 0.4);   // matches jnp f32 promotion
    const float* base = xyz + (size_t)b*NN*3;
    int ctr = indices[gw];
    float cx = base[ctr*3+0], cy = base[ctr*3+1], cz = base[ctr*3+2];
    if (lane < 3) out_newxyz[gw*3 + lane] = base[ctr*3+lane];

    int cnt = 0, first = 0;
    int* myidx = g_idx + (size_t)gw*KK;
    for (int j0 = 0; j0 < NN; j0 += 32) {
        int j = j0 + lane;
        float dx = base[j*3+0]-cx, dy = base[j*3+1]-cy, dz = base[j*3+2]-cz;
        float d2 = dx*dx + dy*dy + dz*dz;
        bool within = d2 < R2;
        unsigned mask = __ballot_sync(0xffffffffu, within);
        if (mask) {
            if (cnt == 0) first = j0 + __ffs(mask) - 1;
            int pre = __popc(mask & ((1u << lane) - 1u));
            if (within && (cnt + pre) < KK) myidx[cnt + pre] = j;
            cnt += __popc(mask);
            if (cnt >= KK) break;
        }
    }
    int ce = cnt < KK ? cnt : KK;
    if (lane >= ce) myidx[lane] = first;
}

// ---------------------------------------------------------------------------
// 3) gather rows of X1: [dxyz(3) | feat(128) | zeros(5)], warp per point
// ---------------------------------------------------------------------------
__global__ void gather_kernel(const float* __restrict__ xyz,
                              const float* __restrict__ newxyz) {
    int r    = (blockIdx.x * blockDim.x + threadIdx.x) >> 5;
    int lane = threadIdx.x & 31;
    if (r >= RROWS) return;
    int b = r >> 15;                       // M*K = 32768
    int j = g_idx[r];
    const float* p = xyz   + ((size_t)b*NN + j)*3;
    const float* c = newxyz + (size_t)(r >> 5)*3;   // group = r/K
    float* xr = g_X1 + (size_t)r*KPAD1;
    if (lane < 3) xr[lane] = p[lane] - c[lane];
    const float* fr = g_featT + ((size_t)b*NN + j)*CC;
    #pragma unroll
    for (int cc = lane; cc < CC; cc += 32) xr[3 + cc] = fr[cc];
    if (lane < 5) xr[131 + lane] = 0.f;
}

// ---------------------------------------------------------------------------
// 4) pad w1 (128x131) -> (128x136)
// ---------------------------------------------------------------------------
__global__ void pad_w1_kernel(const float* __restrict__ w1) {
    int o = blockIdx.x, c = threadIdx.x;   // <<<128,136>>>
    g_w1p[o*KPAD1 + c] = (c < 131) ? w1[o*131 + c] : 0.f;
}

// ---------------------------------------------------------------------------
// GEMM: Y[R x Cout] = act(A) @ W^T + bias.
//  act = identity, or relu(bn_a[k]*x + bn_c[k]) when bn_a != nullptr.
//  128x128 tile, BK=8, 256 threads, 8x8 per thread, fp32.
// ---------------------------------------------------------------------------
__global__ __launch_bounds__(256, 2)
void gemm_bn_kernel(const float* __restrict__ A, int lda,
                    const float* __restrict__ W, int ldw,
                    const float* __restrict__ bias,
                    const float* __restrict__ bn_a,
                    const float* __restrict__ bn_c,
                    float* __restrict__ Y, int Kdim, int Cout) {
    __shared__ float As[8][128];
    __shared__ float Bs[8][128];
    __shared__ float s_bna[KPAD1], s_bnc[KPAD1];

    int tid = threadIdx.x;
    bool use_bn = (bn_a != nullptr);
    if (use_bn) {
        for (int k = tid; k < Kdim; k += 256) { s_bna[k] = bn_a[k]; s_bnc[k] = bn_c[k]; }
    }
    __syncthreads();

    int rowTile = blockIdx.x * 128;
    int colTile = blockIdx.y * 128;
    int arow = tid >> 1;
    int aseg = (tid & 1) * 4;
    const float* Aptr = A + (size_t)(rowTile + arow)*lda + aseg;
    const float* Wptr = W + (size_t)(colTile + arow)*ldw + aseg;
    int tx = tid & 15, ty = tid >> 4;

    float acc[8][8];
    #pragma unroll
    for (int i = 0; i < 8; i++)
        #pragma unroll
        for (int j = 0; j < 8; j++) acc[i][j] = 0.f;

    for (int k0 = 0; k0 < Kdim; k0 += 8) {
        float4 av = *(const float4*)(Aptr + k0);
        float4 wv = *(const float4*)(Wptr + k0);
        if (use_bn) {
            int kb = k0 + aseg;
            av.x = fmaxf(fmaf(av.x, s_bna[kb+0], s_bnc[kb+0]), 0.f);
            av.y = fmaxf(fmaf(av.y, s_bna[kb+1], s_bnc[kb+1]), 0.f);
            av.z = fmaxf(fmaf(av.z, s_bna[kb+2], s_bnc[kb+2]), 0.f);
            av.w = fmaxf(fmaf(av.w, s_bna[kb+3], s_bnc[kb+3]), 0.f);
        }
        As[aseg+0][arow] = av.x; As[aseg+1][arow] = av.y;
        As[aseg+2][arow] = av.z; As[aseg+3][arow] = av.w;
        Bs[aseg+0][arow] = wv.x; Bs[aseg+1][arow] = wv.y;
        Bs[aseg+2][arow] = wv.z; Bs[aseg+3][arow] = wv.w;
        __syncthreads();
        #pragma unroll
        for (int kk = 0; kk < 8; kk++) {
            float ar[8], br[8];
            *(float4*)&ar[0] = *(const float4*)&As[kk][ty*8];
            *(float4*)&ar[4] = *(const float4*)&As[kk][ty*8+4];
            *(float4*)&br[0] = *(const float4*)&Bs[kk][tx*8];
            *(float4*)&br[4] = *(const float4*)&Bs[kk][tx*8+4];
            #pragma unroll
            for (int i = 0; i < 8; i++)
                #pragma unroll
                for (int j = 0; j < 8; j++)
                    acc[i][j] = fmaf(ar[i], br[j], acc[i][j]);
        }
        __syncthreads();
    }

    int col = colTile + tx*8;
    float bsv[8];
    #pragma unroll
    for (int j = 0; j < 8; j++) bsv[j] = bias[col+j];
    #pragma unroll
    for (int i = 0; i < 8; i++) {
        int row = rowTile + ty*8 + i;
        float4 o1, o2;
        o1.x = acc[i][0]+bsv[0]; o1.y = acc[i][1]+bsv[1];
        o1.z = acc[i][2]+bsv[2]; o1.w = acc[i][3]+bsv[3];
        o2.x = acc[i][4]+bsv[4]; o2.y = acc[i][5]+bsv[5];
        o2.z = acc[i][6]+bsv[6]; o2.w = acc[i][7]+bsv[7];
        float* yp = Y + (size_t)row*Cout + col;
        *(float4*)(yp)     = o1;
        *(float4*)(yp + 4) = o2;
    }
}

// ---------------------------------------------------------------------------
// Deterministic BN stats: per-block partial sums, fixed-order finalize
// ---------------------------------------------------------------------------
__global__ void stats_kernel(const float* __restrict__ Y, int C) {
    int c = threadIdx.x;                     // blockDim.x == C
    size_t r0 = (size_t)blockIdx.x * STAT_ROWS;
    float s = 0.f, s2 = 0.f;
    for (int i = 0; i < STAT_ROWS; i++) {
        float v = Y[(r0 + i)*C + c];
        s += v; s2 += v*v;
    }
    g_part[((size_t)blockIdx.x*2 + 0)*C + c] = s;
    g_part[((size_t)blockIdx.x*2 + 1)*C + c] = s2;
}

__global__ void bn_finalize_kernel(int C,
                                   const float* __restrict__ g,
                                   const float* __restrict__ beta,
                                   float* __restrict__ bn_a,
                                   float* __restrict__ bn_c) {
    int c = threadIdx.x;
    float s = 0.f, s2 = 0.f;
    for (int b = 0; b < STAT_BLOCKS; b++) {
        s  += g_part[((size_t)b*2 + 0)*C + c];
        s2 += g_part[((size_t)b*2 + 1)*C + c];
    }
    const float invR = 1.0f / (float)RROWS;
    float mu  = s * invR;
    float var = s2 * invR - mu*mu;
    float a = g[c] * rsqrtf(var + 1e-5f);
    bn_a[c] = a;
    bn_c[c] = beta[c] - a*mu;
}

// ---------------------------------------------------------------------------
// Final: relu(bn(Y3)) max over K -> out[12288 + (b*256+co)*M + m]
// ---------------------------------------------------------------------------
__global__ void maxpool_kernel(const float* __restrict__ bn_a,
                               const float* __restrict__ bn_c,
                               float* __restrict__ out) {
    int grp = blockIdx.x;        // b*M + m
    int co  = threadIdx.x;       // 256
    float a = bn_a[co], c = bn_c[co];
    const float* base = g_Y3 + (size_t)grp*KK*COUT3 + co;
    float mx = 0.f;              // relu floor
    #pragma unroll
    for (int k = 0; k < KK; k++)
        mx = fmaxf(mx, fmaf(a, base[(size_t)k*COUT3], c));
    int b = grp >> 10, m = grp & 1023;
    out[OUT_XYZ_ELEMS + ((size_t)(b*COUT3 + co))*MM + m] = mx;
}

// ---------------------------------------------------------------------------
// host launcher
// ---------------------------------------------------------------------------
extern "C" void kernel_launch(void* const* d_in, const int* in_sizes, int n_in,
                              void* d_out, int out_size) {
    const float* xyz     = (const float*)d_in[0];
    const float* feat    = (const float*)d_in[1];
    const int*   indices = (const int*)  d_in[2];
    const float* w1 = (const float*)d_in[3];
    const float* b1 = (const float*)d_in[4];
    const float* g1 = (const float*)d_in[5];
    const float* e1 = (const float*)d_in[6];
    const float* w2 = (const float*)d_in[7];
    const float* b2 = (const float*)d_in[8];
    const float* g2 = (const float*)d_in[9];
    const float* e2 = (const float*)d_in[10];
    const float* w3 = (const float*)d_in[11];
    const float* b3 = (const float*)d_in[12];
    const float* g3 = (const float*)d_in[13];
    const float* e3 = (const float*)d_in[14];
    float* out = (float*)d_out;

    float *X1, *Y1, *Y2, *Y3, *w1p, *bn;
    cudaGetSymbolAddress((void**)&X1,  g_X1);
    cudaGetSymbolAddress((void**)&Y1,  g_Y1);
    cudaGetSymbolAddress((void**)&Y2,  g_Y2);
    cudaGetSymbolAddress((void**)&Y3,  g_Y3);
    cudaGetSymbolAddress((void**)&w1p, g_w1p);
    cudaGetSymbolAddress((void**)&bn,  g_bn);
    float* a1 = bn;            float* c1 = bn + COUT3;
    float* a2 = bn + 2*COUT3;  float* c2 = bn + 3*COUT3;
    float* a3 = bn + 4*COUT3;  float* c3 = bn + 5*COUT3;

    // prep
    pad_w1_kernel<<<COUT1, KPAD1>>>(w1);
    {
        dim3 blk(32, 32);
        dim3 grd(NN/32, CC/32, BB);
        transpose_feat_kernel<<<grd, blk>>>(feat);
    }
    ballquery_kernel<<<(BB*MM*32)/256, 256>>>(xyz, indices, out);
    gather_kernel<<<(RROWS*32)/256, 256>>>(xyz, out);

    // layer 1: 131(pad 136) -> 128
    gemm_bn_kernel<<<dim3(RROWS/128, COUT1/128), 256>>>(
        X1, KPAD1, w1p, KPAD1, b1, nullptr, nullptr, Y1, KPAD1, COUT1);
    stats_kernel<<<STAT_BLOCKS, COUT1>>>(Y1, COUT1);
    bn_finalize_kernel<<<1, COUT1>>>(COUT1, g1, e1, a1, c1);

    // layer 2: 128 -> 128 (BN+ReLU of Y1 fused into A-load)
    gemm_bn_kernel<<<dim3(RROWS/128, COUT2/128), 256>>>(
        Y1, COUT1, w2, COUT1, b2, a1, c1, Y2, COUT1, COUT2);
    stats_kernel<<<STAT_BLOCKS, COUT2>>>(Y2, COUT2);
    bn_finalize_kernel<<<1, COUT2>>>(COUT2, g2, e2, a2, c2);

    // layer 3: 128 -> 256
    gemm_bn_kernel<<<dim3(RROWS/128, COUT3/128), 256>>>(
        Y2, COUT2, w3, COUT2, b3, a2, c2, Y3, COUT2, COUT3);
    stats_kernel<<<STAT_BLOCKS, COUT3>>>(Y3, COUT3);
    bn_finalize_kernel<<<1, COUT3>>>(COUT3, g3, e3, a3, c3);

    // BN+ReLU+max over K
    maxpool_kernel<<<BB*MM, COUT3>>>(a3, c3, out);
}

// round 2
// speedup vs baseline: 1.2524x; 1.2524x over previous
#include <cuda_runtime.h>
#include <cuda_bf16.h>
#include <math.h>

// ---------------------------------------------------------------------------
// Problem constants
// ---------------------------------------------------------------------------
#define BB 4
#define NN 16384
#define CC 128
#define MM 1024
#define KK 32
#define RROWS (BB*MM*KK)        // 131072
#define KPAD1 136               // 131 padded to multiple of 8
#define COUT1 128
#define COUT2 128
#define COUT3 256
#define NBLK (RROWS/128)        // 1024 row-tiles
#define NGRP (BB*MM)            // 4096 groups
#define OUT_XYZ_ELEMS (BB*MM*3) // 12288

// ---------------------------------------------------------------------------
// Scratch (static device globals -- no allocation APIs allowed)
// ---------------------------------------------------------------------------
__device__ float g_featT[(size_t)BB*NN*CC];       // 32 MB   (B,N,C)
__device__ int   g_idx[(size_t)BB*MM*KK];         // 512 KB
__device__ float g_Y1[(size_t)RROWS*COUT1];       // 64 MB
__device__ float g_Y2[(size_t)RROWS*COUT2];       // 64 MB
__device__ float g_gmax[(size_t)NGRP*COUT3];      // 4 MB (pre-BN max over K)
__device__ float g_w1p[COUT1*KPAD1];
__device__ float g_part[(size_t)NBLK*2*COUT3];    // per-row-tile stats partials (2MB)
__device__ float g_bn[6*COUT3];                   // a1,c1,a2,c2,a3,c3

// ---------------------------------------------------------------------------
// 1) transpose features (B,C,N) -> (B,N,C)
// ---------------------------------------------------------------------------
__global__ void transpose_feat_kernel(const float* __restrict__ f) {
    __shared__ float tile[32][33];
    int b  = blockIdx.z;
    int n0 = blockIdx.x * 32;
    int c0 = blockIdx.y * 32;
    int tx = threadIdx.x, ty = threadIdx.y;
    tile[ty][tx] = f[((size_t)b*CC + (c0+ty))*NN + (n0+tx)];
    __syncthreads();
    g_featT[((size_t)b*NN + (n0+ty))*CC + (c0+tx)] = tile[tx][ty];
}

// ---------------------------------------------------------------------------
// 2) ball query: warp per query. Writes new_xyz directly into d_out[0:12288)
// ---------------------------------------------------------------------------
__global__ void ballquery_kernel(const float* __restrict__ xyz,
                                 const int*   __restrict__ indices,
                                 float*       __restrict__ out_newxyz) {
    int gw   = (blockIdx.x * blockDim.x + threadIdx.x) >> 5;
    int lane = threadIdx.x & 31;
    if (gw >= BB*MM) return;
    int b = gw >> 10;                 // MM = 1024
    const float R2 = (float)(0.4 * 0.4);
    const float* base = xyz + (size_t)b*NN*3;
    int ctr = indices[gw];
    float cx = base[ctr*3+0], cy = base[ctr*3+1], cz = base[ctr*3+2];
    if (lane < 3) out_newxyz[gw*3 + lane] = base[ctr*3+lane];

    int cnt = 0, first = 0;
    int* myidx = g_idx + (size_t)gw*KK;
    for (int j0 = 0; j0 < NN; j0 += 32) {
        int j = j0 + lane;
        float dx = base[j*3+0]-cx, dy = base[j*3+1]-cy, dz = base[j*3+2]-cz;
        float d2 = dx*dx + dy*dy + dz*dz;
        bool within = d2 < R2;
        unsigned mask = __ballot_sync(0xffffffffu, within);
        if (mask) {
            if (cnt == 0) first = j0 + __ffs(mask) - 1;
            int pre = __popc(mask & ((1u << lane) - 1u));
            if (within && (cnt + pre) < KK) myidx[cnt + pre] = j;
            cnt += __popc(mask);
            if (cnt >= KK) break;
        }
    }
    int ce = cnt < KK ? cnt : KK;
    if (lane >= ce) myidx[lane] = first;
}

// ---------------------------------------------------------------------------
// 3) pad+permute w1 (128x131) -> (128x136):
//    k in [0,128)   <- w1[:, 3+k]   (feature channels)
//    k in [128,131) <- w1[:, k-128] (dxyz)
//    k in [131,136) <- 0
// ---------------------------------------------------------------------------
__global__ void pad_w1_kernel(const float* __restrict__ w1) {
    int o = blockIdx.x, k = threadIdx.x;   // <<<128,136>>>
    float v;
    if (k < 128)      v = w1[o*131 + 3 + k];
    else if (k < 131) v = w1[o*131 + (k - 128)];
    else              v = 0.f;
    g_w1p[o*KPAD1 + k] = v;
}

// ---------------------------------------------------------------------------
// Fused GEMM: Y[R x Cout] = act(A) @ W^T + bias, plus epilogue stats
// (per-tile column sum / sumsq) and, for MODE 2, per-group max-pool.
//   MODE 0: A is the virtual gathered X1 (featT + dxyz), no input BN.
//   MODE 1: A = Y1, input act = relu(bn_a*x + bn_c). Writes Y.
//   MODE 2: A = Y2, input act = relu(bn), NO Y write; writes g_gmax.
// 128x128 tile, BK=8, 256 threads, 8x8 per thread, fp32.
// ---------------------------------------------------------------------------
template<int MODE>
__global__ __launch_bounds__(256, 2)
void gemm_fused(const float* __restrict__ A, int lda,
                const float* __restrict__ W, int ldw,
                const float* __restrict__ bias,
                const float* __restrict__ bn_a,
                const float* __restrict__ bn_c,
                float* __restrict__ Y,
                const float* __restrict__ xyz,
                const float* __restrict__ newxyz,
                int Kdim, int CoutTotal) {
    __shared__ float As[8][128];
    __shared__ float Bs[8][128];
    __shared__ float s_bna[128], s_bnc[128];
    __shared__ float red_s[16][128];
    __shared__ float red_q[16][128];
    __shared__ float red_m[16][128];

    int tid = threadIdx.x;
    if (MODE != 0) {
        if (tid < 128) { s_bna[tid] = bn_a[tid]; s_bnc[tid] = bn_c[tid]; }
        __syncthreads();
    }

    int rowTile = blockIdx.x * 128;
    int colTile = blockIdx.y * 128;
    int arow = tid >> 1;
    int aseg = (tid & 1) * 4;

    // ----- A-side addressing -----
    const float* Aptr = nullptr;
    const float* fb = nullptr;
    float dxv = 0.f, dyv = 0.f, dzv = 0.f;
    if (MODE == 0) {
        int r  = rowTile + arow;
        int bb = r >> 15;                          // M*K = 32768
        int jj = g_idx[r];
        fb = g_featT + ((size_t)bb*NN + jj)*CC;
        const float* pp = xyz   + ((size_t)bb*NN + jj)*3;
        const float* cq = newxyz + (size_t)(r >> 5)*3;
        dxv = pp[0]-cq[0]; dyv = pp[1]-cq[1]; dzv = pp[2]-cq[2];
    } else {
        Aptr = A + (size_t)(rowTile + arow)*lda + aseg;
    }
    const float* Wptr = W + (size_t)(colTile + arow)*ldw + aseg;

    int tx = tid & 15, ty = tid >> 4;

    float acc[8][8];
    #pragma unroll
    for (int i = 0; i < 8; i++)
        #pragma unroll
        for (int j = 0; j < 8; j++) acc[i][j] = 0.f;

    for (int k0 = 0; k0 < Kdim; k0 += 8) {
        float4 av;
        if (MODE == 0) {
            if (k0 < 128) av = *(const float4*)(fb + k0 + aseg);
            else av = (aseg == 0) ? make_float4(dxv, dyv, dzv, 0.f)
                                  : make_float4(0.f, 0.f, 0.f, 0.f);
        } else {
            av = *(const float4*)(Aptr + k0);
            int kb = k0 + aseg;
            av.x = fmaxf(fmaf(av.x, s_bna[kb+0], s_bnc[kb+0]), 0.f);
            av.y = fmaxf(fmaf(av.y, s_bna[kb+1], s_bnc[kb+1]), 0.f);
            av.z = fmaxf(fmaf(av.z, s_bna[kb+2], s_bnc[kb+2]), 0.f);
            av.w = fmaxf(fmaf(av.w, s_bna[kb+3], s_bnc[kb+3]), 0.f);
        }
        float4 wv = *(const float4*)(Wptr + k0);
        As[aseg+0][arow] = av.x; As[aseg+1][arow] = av.y;
        As[aseg+2][arow] = av.z; As[aseg+3][arow] = av.w;
        Bs[aseg+0][arow] = wv.x; Bs[aseg+1][arow] = wv.y;
        Bs[aseg+2][arow] = wv.z; Bs[aseg+3][arow] = wv.w;
        __syncthreads();
        #pragma unroll
        for (int kk = 0; kk < 8; kk++) {
            float ar[8], br[8];
            *(float4*)&ar[0] = *(const float4*)&As[kk][ty*8];
            *(float4*)&ar[4] = *(const float4*)&As[kk][ty*8+4];
            *(float4*)&br[0] = *(const float4*)&Bs[kk][tx*8];
            *(float4*)&br[4] = *(const float4*)&Bs[kk][tx*8+4];
            #pragma unroll
            for (int i = 0; i < 8; i++)
                #pragma unroll
                for (int j = 0; j < 8; j++)
                    acc[i][j] = fmaf(ar[i], br[j], acc[i][j]);
        }
        __syncthreads();
    }

    // ----- epilogue: bias, stats (and max for MODE 2), optional Y write -----
    int colbase = colTile + tx*8;
    float bsv[8];
    #pragma unroll
    for (int j = 0; j < 8; j++) bsv[j] = bias[colbase + j];

    float s8[8], q8[8], m8[8];
    #pragma unroll
    for (int j = 0; j < 8; j++) { s8[j] = 0.f; q8[j] = 0.f; m8[j] = -3.4e38f; }
    #pragma unroll
    for (int i = 0; i < 8; i++) {
        #pragma unroll
        for (int j = 0; j < 8; j++) {
            float v = acc[i][j] + bsv[j];
            acc[i][j] = v;
            s8[j] += v;
            q8[j] = fmaf(v, v, q8[j]);
            if (MODE == 2) m8[j] = fmaxf(m8[j], v);
        }
    }

    if (MODE != 2) {
        #pragma unroll
        for (int i = 0; i < 8; i++) {
            int row = rowTile + ty*8 + i;
            float* yp = Y + (size_t)row*CoutTotal + colbase;
            float4 o1, o2;
            o1.x = acc[i][0]; o1.y = acc[i][1]; o1.z = acc[i][2]; o1.w = acc[i][3];
            o2.x = acc[i][4]; o2.y = acc[i][5]; o2.z = acc[i][6]; o2.w = acc[i][7];
            *(float4*)(yp)     = o1;
            *(float4*)(yp + 4) = o2;
        }
    }

    #pragma unroll
    for (int j = 0; j < 8; j++) {
        red_s[ty][tx*8+j] = s8[j];
        red_q[ty][tx*8+j] = q8[j];
        if (MODE == 2) red_m[ty][tx*8+j] = m8[j];
    }
    __syncthreads();

    if (tid < 128) {
        int c = tid;
        float ss = 0.f, qq = 0.f;
        #pragma unroll
        for (int t = 0; t < 16; t++) { ss += red_s[t][c]; qq += red_q[t][c]; }
        size_t pbase = (size_t)blockIdx.x * (2*CoutTotal);
        g_part[pbase + colTile + c]             = ss;
        g_part[pbase + CoutTotal + colTile + c] = qq;
        if (MODE == 2) {
            // 4 complete K=32 groups per 128-row tile: ty in [gl*4, gl*4+4)
            #pragma unroll
            for (int gl = 0; gl < 4; gl++) {
                float mm = red_m[gl*4+0][c];
                mm = fmaxf(mm, red_m[gl*4+1][c]);
                mm = fmaxf(mm, red_m[gl*4+2][c]);
                mm = fmaxf(mm, red_m[gl*4+3][c]);
                g_gmax[((size_t)(blockIdx.x*4 + gl))*COUT3 + colTile + c] = mm;
            }
        }
    }
}

// ---------------------------------------------------------------------------
// BN finalize: one block per channel, fixed-order tree reduce over NBLK partials
// ---------------------------------------------------------------------------
__global__ void bn_finalize_kernel(int C,
                                   const float* __restrict__ g,
                                   const float* __restrict__ beta,
                                   float* __restrict__ bn_a,
                                   float* __restrict__ bn_c) {
    __shared__ float sh_s[256], sh_q[256];
    int ch = blockIdx.x;
    int t  = threadIdx.x;
    float s = 0.f, q = 0.f;
    for (int b = t; b < NBLK; b += 256) {
        size_t base = (size_t)b * (2*C);
        s += g_part[base + ch];
        q += g_part[base + C + ch];
    }
    sh_s[t] = s; sh_q[t] = q;
    __syncthreads();
    for (int off = 128; off > 0; off >>= 1) {
        if (t < off) { sh_s[t] += sh_s[t+off]; sh_q[t] += sh_q[t+off]; }
        __syncthreads();
    }
    if (t == 0) {
        const float invR = 1.0f / (float)RROWS;
        float mu  = sh_s[0] * invR;
        float var = sh_q[0] * invR - mu*mu;
        float a = g[ch] * rsqrtf(var + 1e-5f);
        bn_a[ch] = a;
        bn_c[ch] = beta[ch] - a*mu;
    }
}

// ---------------------------------------------------------------------------
// Final: relu(a3*gmax + c3) -> out[12288 + (b*256+co)*M + m]
// (valid because a3 > 0 -> BN+relu commute with max over K)
// ---------------------------------------------------------------------------
__global__ void final_out_kernel(const float* __restrict__ bn_a,
                                 const float* __restrict__ bn_c,
                                 float* __restrict__ out) {
    int grp = blockIdx.x;        // b*M + m
    int co  = threadIdx.x;       // 256
    float v = g_gmax[(size_t)grp*COUT3 + co];
    float r = fmaxf(fmaf(bn_a[co], v, bn_c[co]), 0.f);
    int b = grp >> 10, m = grp & 1023;
    out[OUT_XYZ_ELEMS + ((size_t)(b*COUT3 + co))*MM + m] = r;
}

// ---------------------------------------------------------------------------
// host launcher
// ---------------------------------------------------------------------------
extern "C" void kernel_launch(void* const* d_in, const int* in_sizes, int n_in,
                              void* d_out, int out_size) {
    const float* xyz     = (const float*)d_in[0];
    const float* feat    = (const float*)d_in[1];
    const int*   indices = (const int*)  d_in[2];
    const float* w1 = (const float*)d_in[3];
    const float* b1 = (const float*)d_in[4];
    const float* g1 = (const float*)d_in[5];
    const float* e1 = (const float*)d_in[6];
    const float* w2 = (const float*)d_in[7];
    const float* b2 = (const float*)d_in[8];
    const float* g2 = (const float*)d_in[9];
    const float* e2 = (const float*)d_in[10];
    const float* w3 = (const float*)d_in[11];
    const float* b3 = (const float*)d_in[12];
    const float* g3 = (const float*)d_in[13];
    const float* e3 = (const float*)d_in[14];
    float* out = (float*)d_out;

    float *Y1, *Y2, *w1p, *bn;
    cudaGetSymbolAddress((void**)&Y1,  g_Y1);
    cudaGetSymbolAddress((void**)&Y2,  g_Y2);
    cudaGetSymbolAddress((void**)&w1p, g_w1p);
    cudaGetSymbolAddress((void**)&bn,  g_bn);
    float* a1 = bn;            float* c1 = bn + COUT3;
    float* a2 = bn + 2*COUT3;  float* c2 = bn + 3*COUT3;
    float* a3 = bn + 4*COUT3;  float* c3 = bn + 5*COUT3;

    // prep
    pad_w1_kernel<<<COUT1, KPAD1>>>(w1);
    {
        dim3 blk(32, 32);
        dim3 grd(NN/32, CC/32, BB);
        transpose_feat_kernel<<<grd, blk>>>(feat);
    }
    ballquery_kernel<<<(BB*MM*32)/256, 256>>>(xyz, indices, out);

    // layer 1: virtual-gathered 136 -> 128, stats fused
    gemm_fused<0><<<dim3(NBLK, 1), 256>>>(
        nullptr, 0, w1p, KPAD1, b1, nullptr, nullptr, Y1, xyz, out, KPAD1, COUT1);
    bn_finalize_kernel<<<COUT1, 256>>>(COUT1, g1, e1, a1, c1);

    // layer 2: 128 -> 128 (BN1+ReLU fused into A-load), stats fused
    gemm_fused<1><<<dim3(NBLK, 1), 256>>>(
        Y1, COUT1, w2, COUT1, b2, a1, c1, Y2, nullptr, nullptr, COUT1, COUT2);
    bn_finalize_kernel<<<COUT2, 256>>>(COUT2, g2, e2, a2, c2);

    // layer 3: 128 -> 256 (BN2+ReLU fused), stats + maxpool fused, no Y3
    gemm_fused<2><<<dim3(NBLK, 2), 256>>>(
        Y2, COUT2, w3, COUT2, b3, a2, c2, nullptr, nullptr, nullptr, COUT2, COUT3);
    bn_finalize_kernel<<<COUT3, 256>>>(COUT3, g3, e3, a3, c3);

    // BN3 + ReLU on pooled maxima
    final_out_kernel<<<NGRP, COUT3>>>(a3, c3, out);
}

// round 3
// speedup vs baseline: 1.6822x; 1.3432x over previous
#include <cuda_runtime.h>
#include <cuda_bf16.h>
#include <math.h>
#include <stdint.h>

// ---------------------------------------------------------------------------
// Problem constants
// ---------------------------------------------------------------------------
#define BB 4
#define NN 16384
#define CC 128
#define MM 1024
#define KK 32
#define RROWS (BB*MM*KK)        // 131072
#define COUT1 128
#define COUT2 128
#define COUT3 256
#define NBLK (RROWS/128)        // 1024 row-tiles
#define NGRP (BB*MM)            // 4096 groups
#define OUT_XYZ_ELEMS (BB*MM*3) // 12288
#define KP1 144                 // layer1 logical K padded (131 -> 144)
#define KP23 128

// ---------------------------------------------------------------------------
// Scratch (static device globals -- no allocation APIs allowed)
// ---------------------------------------------------------------------------
__device__ float g_featT[(size_t)BB*NN*CC];        // 32 MB (B,N,C)
__device__ int   g_idx[(size_t)BB*MM*KK];          // 512 KB
__device__ float g_Y1[(size_t)RROWS*COUT1];        // 64 MB
__device__ float g_Y2[(size_t)RROWS*COUT2];        // 64 MB
__device__ float g_gmax[(size_t)NGRP*COUT3];       // 4 MB
__device__ __nv_bfloat16 g_w1s[COUT1*3*KP1];       // split weights, interleaved
__device__ __nv_bfloat16 g_w2s[COUT2*3*KP23];
__device__ __nv_bfloat16 g_w3s[COUT3*3*KP23];
__device__ float g_part[(size_t)NBLK*2*COUT3];     // per-row-tile stats partials
__device__ float g_bn[6*COUT3];                    // a1,c1,a2,c2,a3,c3

// ---------------------------------------------------------------------------
// helpers
// ---------------------------------------------------------------------------
__device__ __forceinline__ uint32_t bf2(float x, float y) {
    __nv_bfloat162 t = __floats2bfloat162_rn(x, y);
    return *reinterpret_cast<uint32_t*>(&t);
}

__device__ __forceinline__ void mma16816(float* c,
        uint32_t a0, uint32_t a1, uint32_t a2, uint32_t a3,
        uint32_t b0, uint32_t b1) {
    asm volatile(
        "mma.sync.aligned.m16n8k16.row.col.f32.bf16.bf16.f32 "
        "{%0,%1,%2,%3}, {%4,%5,%6,%7}, {%8,%9}, {%0,%1,%2,%3};\n"
        : "+f"(c[0]), "+f"(c[1]), "+f"(c[2]), "+f"(c[3])
        : "r"(a0), "r"(a1), "r"(a2), "r"(a3), "r"(b0), "r"(b1));
}

// ---------------------------------------------------------------------------
// 1) transpose features (B,C,N) -> (B,N,C)
// ---------------------------------------------------------------------------
__global__ void transpose_feat_kernel(const float* __restrict__ f) {
    __shared__ float tile[32][33];
    int b  = blockIdx.z;
    int n0 = blockIdx.x * 32;
    int c0 = blockIdx.y * 32;
    int tx = threadIdx.x, ty = threadIdx.y;
    tile[ty][tx] = f[((size_t)b*CC + (c0+ty))*NN + (n0+tx)];
    __syncthreads();
    g_featT[((size_t)b*NN + (n0+ty))*CC + (c0+tx)] = tile[tx][ty];
}

// ---------------------------------------------------------------------------
// 2) ball query: warp per query. Writes new_xyz directly into d_out[0:12288)
// ---------------------------------------------------------------------------
__global__ void ballquery_kernel(const float* __restrict__ xyz,
                                 const int*   __restrict__ indices,
                                 float*       __restrict__ out_newxyz) {
    int gw   = (blockIdx.x * blockDim.x + threadIdx.x) >> 5;
    int lane = threadIdx.x & 31;
    if (gw >= BB*MM) return;
    int b = gw >> 10;
    const float R2 = (float)(0.4 * 0.4);
    const float* base = xyz + (size_t)b*NN*3;
    int ctr = indices[gw];
    float cx = base[ctr*3+0], cy = base[ctr*3+1], cz = base[ctr*3+2];
    if (lane < 3) out_newxyz[gw*3 + lane] = base[ctr*3+lane];

    int cnt = 0, first = 0;
    int* myidx = g_idx + (size_t)gw*KK;
    for (int j0 = 0; j0 < NN; j0 += 32) {
        int j = j0 + lane;
        float dx = base[j*3+0]-cx, dy = base[j*3+1]-cy, dz = base[j*3+2]-cz;
        float d2 = dx*dx + dy*dy + dz*dz;
        bool within = d2 < R2;
        unsigned mask = __ballot_sync(0xffffffffu, within);
        if (mask) {
            if (cnt == 0) first = j0 + __ffs(mask) - 1;
            int pre = __popc(mask & ((1u << lane) - 1u));
            if (within && (cnt + pre) < KK) myidx[cnt + pre] = j;
            cnt += __popc(mask);
            if (cnt >= KK) break;
        }
    }
    int ce = cnt < KK ? cnt : KK;
    if (lane >= ce) myidx[lane] = first;
}

// ---------------------------------------------------------------------------
// 3) weight split:  out[o][c*48 + {kk, 16+kk, 32+kk}] = {hi, lo, hi}
//    perm=1 (layer1): logical k<128 -> w[o][3+k]; 128..130 -> w[o][k-128]; else 0
// ---------------------------------------------------------------------------
__global__ void splitw_kernel(const float* __restrict__ w,
                              __nv_bfloat16* __restrict__ out,
                              int Cin, int KP, int perm) {
    int o = blockIdx.x, k = threadIdx.x;       // KP threads
    float v;
    if (perm) {
        if (k < 128)      v = w[o*Cin + 3 + k];
        else if (k < 131) v = w[o*Cin + (k - 128)];
        else              v = 0.f;
    } else {
        v = (k < Cin) ? w[o*Cin + k] : 0.f;
    }
    __nv_bfloat16 h = __float2bfloat16_rn(v);
    __nv_bfloat16 l = __float2bfloat16_rn(v - __bfloat162float(h));
    int c = k >> 4, kk = k & 15;
    __nv_bfloat16* base = out + (size_t)o*3*KP + c*48;
    base[kk]      = h;
    base[16 + kk] = l;
    base[32 + kk] = h;
}

// ---------------------------------------------------------------------------
// Tensor-core fused GEMM.  Y[R x Cout] = act(A) @ W^T + bias
//   MODE 0: A = virtual gathered X1 (featT + dxyz), no act.  NCHUNK=9.
//   MODE 1: A = Y1, act = relu(bn_a*x+bn_c).  Writes Y.     NCHUNK=8.
//   MODE 2: A = Y2, act = relu(bn).  No Y; writes g_gmax.   NCHUNK=8.
// Split precision: per logical 16-k chunk, 3 bf16 segments:
//   A: [hi, hi, lo]   W: [hi, lo, hi]  ->  hi*hi + hi*lo + lo*hi
// Block 128x128, 8 warps of 32x64, m16n8k16 bf16 mma, fp32 accum.
// ---------------------------------------------------------------------------
template<int MODE, int NCHUNK>
__global__ __launch_bounds__(256, 2)
void gemm_mma(const float* __restrict__ A,
              const __nv_bfloat16* __restrict__ Wsp, int KP3,
              const float* __restrict__ bias,
              const float* __restrict__ bn_a, const float* __restrict__ bn_c,
              float* __restrict__ Y,
              const float* __restrict__ xyz, const float* __restrict__ newxyz,
              int CoutTotal) {
    // smem: 56-bf16 (28-word) row stride -> conflict-free fragment LDS
    __shared__ uint32_t AsW[128*28];
    __shared__ uint32_t WsW[128*28];
    __shared__ float red_s[4][128];
    __shared__ float red_q[4][128];
    __shared__ float red_m[4][128];
    __shared__ float s_bna[128], s_bnc[128];

    int tid  = threadIdx.x;
    int rowTile = blockIdx.x * 128;
    int colTile = blockIdx.y * 128;

    if (MODE != 0 && tid < 128) { s_bna[tid] = bn_a[tid]; s_bnc[tid] = bn_c[tid]; }
    __syncthreads();

    // ---- loader indices ----
    int row  = tid >> 1;          // 0..127
    int half = tid & 1;           // 0/1 -> 8-float half of 16-k chunk

    const float* fb = nullptr;    // MODE 0 feature base
    float dxv = 0.f, dyv = 0.f, dzv = 0.f;
    const float* aRow = nullptr;
    if (MODE == 0) {
        int r  = rowTile + row;
        int bb = r >> 15;
        int jj = g_idx[r];
        fb = g_featT + ((size_t)bb*NN + jj)*CC + half*8;
        const float* pp = xyz    + ((size_t)bb*NN + jj)*3;
        const float* cq = newxyz + (size_t)(r >> 5)*3;
        dxv = pp[0]-cq[0]; dyv = pp[1]-cq[1]; dzv = pp[2]-cq[2];
    } else {
        aRow = A + (size_t)(rowTile + row)*128 + half*8;
    }
    const __nv_bfloat16* wRow = Wsp + (size_t)(colTile + row)*KP3 + half*24;

    // ---- mma indices ----
    int lane = tid & 31, warp = tid >> 5;
    int wm = warp >> 1, wn = warp & 1;
    int g  = lane >> 2, t = lane & 3;

    float acc[2][8][4];
    #pragma unroll
    for (int mf = 0; mf < 2; mf++)
        #pragma unroll
        for (int nf = 0; nf < 8; nf++)
            #pragma unroll
            for (int r2 = 0; r2 < 4; r2++) acc[mf][nf][r2] = 0.f;

    // ---- chunk load helpers ----
    float4 af0, af1;  uint4 wf0, wf1, wf2;
    auto ldA = [&](int c, float4& f0, float4& f1) {
        if (MODE == 0) {
            if (c < 8) {
                f0 = *(const float4*)(fb + c*16);
                f1 = *(const float4*)(fb + c*16 + 4);
            } else {
                f0 = (half == 0) ? make_float4(dxv, dyv, dzv, 0.f)
                                 : make_float4(0.f, 0.f, 0.f, 0.f);
                f1 = make_float4(0.f, 0.f, 0.f, 0.f);
            }
        } else {
            const float* p = aRow + c*16;
            f0 = *(const float4*)p;
            f1 = *(const float4*)(p + 4);
        }
    };
    auto ldW = [&](int c, uint4& w0, uint4& w1, uint4& w2) {
        const uint4* p = reinterpret_cast<const uint4*>(wRow + c*48);
        w0 = p[0]; w1 = p[1]; w2 = p[2];
    };

    ldA(0, af0, af1);
    ldW(0, wf0, wf1, wf2);

    #pragma unroll 1
    for (int c = 0; c < NCHUNK; c++) {
        // ---- STS current chunk (convert + split A) ----
        {
            float v[8] = {af0.x, af0.y, af0.z, af0.w, af1.x, af1.y, af1.z, af1.w};
            if (MODE != 0) {
                int kb = c*16 + half*8;
                #pragma unroll
                for (int j = 0; j < 8; j++)
                    v[j] = fmaxf(fmaf(v[j], s_bna[kb+j], s_bnc[kb+j]), 0.f);
            }
            float hv[8], lv[8];
            #pragma unroll
            for (int j = 0; j < 8; j++) {
                hv[j] = __bfloat162float(__float2bfloat16_rn(v[j]));
                lv[j] = v[j] - hv[j];
            }
            uint4 hq, lq;
            hq.x = bf2(hv[0], hv[1]); hq.y = bf2(hv[2], hv[3]);
            hq.z = bf2(hv[4], hv[5]); hq.w = bf2(hv[6], hv[7]);
            lq.x = bf2(lv[0], lv[1]); lq.y = bf2(lv[2], lv[3]);
            lq.z = bf2(lv[4], lv[5]); lq.w = bf2(lv[6], lv[7]);
            uint32_t* ab = AsW + row*28 + half*4;
            *(uint4*)(ab + 0)  = hq;     // seg 0: hi
            *(uint4*)(ab + 8)  = hq;     // seg 1: hi
            *(uint4*)(ab + 16) = lq;     // seg 2: lo
            uint32_t* wb = WsW + row*28 + half*12;
            *(uint4*)(wb + 0) = wf0;     // segs already interleaved hi,lo,hi
            *(uint4*)(wb + 4) = wf1;
            *(uint4*)(wb + 8) = wf2;
        }
        __syncthreads();

        // ---- prefetch next chunk ----
        if (c + 1 < NCHUNK) {
            ldA(c + 1, af0, af1);
            ldW(c + 1, wf0, wf1, wf2);
        }

        // ---- mma over 3 segments ----
        #pragma unroll
        for (int s = 0; s < 3; s++) {
            uint32_t a[2][4];
            #pragma unroll
            for (int mf = 0; mf < 2; mf++) {
                int rb = (wm*32 + mf*16 + g)*28 + s*8;
                a[mf][0] = AsW[rb + t];
                a[mf][1] = AsW[rb + 8*28 + t];
                a[mf][2] = AsW[rb + 4 + t];
                a[mf][3] = AsW[rb + 8*28 + 4 + t];
            }
            #pragma unroll
            for (int nf = 0; nf < 8; nf++) {
                int nb = (wn*64 + nf*8 + g)*28 + s*8;
                uint32_t b0 = WsW[nb + t];
                uint32_t b1 = WsW[nb + 4 + t];
                mma16816(acc[0][nf], a[0][0], a[0][1], a[0][2], a[0][3], b0, b1);
                mma16816(acc[1][nf], a[1][0], a[1][1], a[1][2], a[1][3], b0, b1);
            }
        }
        __syncthreads();
    }

    // ---- epilogue: bias, Y write, stats, (max) ----
    float bs[8][2];
    #pragma unroll
    for (int nf = 0; nf < 8; nf++) {
        int col = colTile + wn*64 + nf*8 + 2*t;
        bs[nf][0] = bias[col];
        bs[nf][1] = bias[col+1];
    }

    float s16[8][2], q16[8][2], m16[8][2];
    #pragma unroll
    for (int nf = 0; nf < 8; nf++)
        #pragma unroll
        for (int e = 0; e < 2; e++) { s16[nf][e]=0.f; q16[nf][e]=0.f; m16[nf][e]=-3.4e38f; }

    #pragma unroll
    for (int mf = 0; mf < 2; mf++) {
        #pragma unroll
        for (int nf = 0; nf < 8; nf++) {
            float v0 = acc[mf][nf][0] + bs[nf][0];
            float v1 = acc[mf][nf][1] + bs[nf][1];
            float v2 = acc[mf][nf][2] + bs[nf][0];
            float v3 = acc[mf][nf][3] + bs[nf][1];
            s16[nf][0] += v0 + v2;  s16[nf][1] += v1 + v3;
            q16[nf][0] = fmaf(v0,v0,fmaf(v2,v2,q16[nf][0]));
            q16[nf][1] = fmaf(v1,v1,fmaf(v3,v3,q16[nf][1]));
            m16[nf][0] = fmaxf(m16[nf][0], fmaxf(v0, v2));
            m16[nf][1] = fmaxf(m16[nf][1], fmaxf(v1, v3));
            if (MODE != 2) {
                int r0 = rowTile + wm*32 + mf*16 + g;
                int cb = colTile + wn*64 + nf*8 + 2*t;
                float2* y0 = (float2*)(Y + (size_t)r0*CoutTotal + cb);
                float2* y1 = (float2*)(Y + (size_t)(r0+8)*CoutTotal + cb);
                *y0 = make_float2(v0, v1);
                *y1 = make_float2(v2, v3);
            }
        }
    }

    // warp reduce over g (lane bits 2..4)
    #pragma unroll
    for (int off = 4; off <= 16; off <<= 1) {
        #pragma unroll
        for (int nf = 0; nf < 8; nf++)
            #pragma unroll
            for (int e = 0; e < 2; e++) {
                s16[nf][e] += __shfl_xor_sync(0xffffffffu, s16[nf][e], off);
                q16[nf][e] += __shfl_xor_sync(0xffffffffu, q16[nf][e], off);
                m16[nf][e] = fmaxf(m16[nf][e], __shfl_xor_sync(0xffffffffu, m16[nf][e], off));
            }
    }
    if (g == 0) {
        #pragma unroll
        for (int nf = 0; nf < 8; nf++)
            #pragma unroll
            for (int e = 0; e < 2; e++) {
                int cl = wn*64 + nf*8 + 2*t + e;
                red_s[wm][cl] = s16[nf][e];
                red_q[wm][cl] = q16[nf][e];
                if (MODE == 2) red_m[wm][cl] = m16[nf][e];
            }
    }
    __syncthreads();

    if (tid < 128) {
        int c = tid;
        float ss = red_s[0][c] + red_s[1][c] + red_s[2][c] + red_s[3][c];
        float qq = red_q[0][c] + red_q[1][c] + red_q[2][c] + red_q[3][c];
        size_t pbase = (size_t)blockIdx.x * (2*CoutTotal);
        g_part[pbase + colTile + c]             = ss;
        g_part[pbase + CoutTotal + colTile + c] = qq;
        if (MODE == 2) {
            #pragma unroll
            for (int wmi = 0; wmi < 4; wmi++)
                g_gmax[((size_t)(blockIdx.x*4 + wmi))*COUT3 + colTile + c] = red_m[wmi][c];
        }
    }
}

// ---------------------------------------------------------------------------
// BN finalize: one block per channel, fixed-order reduce over NBLK partials
// ---------------------------------------------------------------------------
__global__ void bn_finalize_kernel(int C,
                                   const float* __restrict__ g,
                                   const float* __restrict__ beta,
                                   float* __restrict__ bn_a,
                                   float* __restrict__ bn_c) {
    __shared__ float sh_s[256], sh_q[256];
    int ch = blockIdx.x;
    int t  = threadIdx.x;
    float s = 0.f, q = 0.f;
    for (int b = t; b < NBLK; b += 256) {
        size_t base = (size_t)b * (2*C);
        s += g_part[base + ch];
        q += g_part[base + C + ch];
    }
    sh_s[t] = s; sh_q[t] = q;
    __syncthreads();
    for (int off = 128; off > 0; off >>= 1) {
        if (t < off) { sh_s[t] += sh_s[t+off]; sh_q[t] += sh_q[t+off]; }
        __syncthreads();
    }
    if (t == 0) {
        const float invR = 1.0f / (float)RROWS;
        float mu  = sh_s[0] * invR;
        float var = sh_q[0] * invR - mu*mu;
        float a = g[ch] * rsqrtf(var + 1e-5f);
        bn_a[ch] = a;
        bn_c[ch] = beta[ch] - a*mu;
    }
}

// ---------------------------------------------------------------------------
// Final: relu(a3*gmax + c3) -> out (a3>0 so BN+relu commute with max)
// ---------------------------------------------------------------------------
__global__ void final_out_kernel(const float* __restrict__ bn_a,
                                 const float* __restrict__ bn_c,
                                 float* __restrict__ out) {
    int grp = blockIdx.x;
    int co  = threadIdx.x;
    float v = g_gmax[(size_t)grp*COUT3 + co];
    float r = fmaxf(fmaf(bn_a[co], v, bn_c[co]), 0.f);
    int b = grp >> 10, m = grp & 1023;
    out[OUT_XYZ_ELEMS + ((size_t)(b*COUT3 + co))*MM + m] = r;
}

// ---------------------------------------------------------------------------
// host launcher
// ---------------------------------------------------------------------------
extern "C" void kernel_launch(void* const* d_in, const int* in_sizes, int n_in,
                              void* d_out, int out_size) {
    const float* xyz     = (const float*)d_in[0];
    const float* feat    = (const float*)d_in[1];
    const int*   indices = (const int*)  d_in[2];
    const float* w1 = (const float*)d_in[3];
    const float* b1 = (const float*)d_in[4];
    const float* g1 = (const float*)d_in[5];
    const float* e1 = (const float*)d_in[6];
    const float* w2 = (const float*)d_in[7];
    const float* b2 = (const float*)d_in[8];
    const float* g2 = (const float*)d_in[9];
    const float* e2 = (const float*)d_in[10];
    const float* w3 = (const float*)d_in[11];
    const float* b3 = (const float*)d_in[12];
    const float* g3 = (const float*)d_in[13];
    const float* e3 = (const float*)d_in[14];
    float* out = (float*)d_out;

    float *Y1, *Y2, *bn;
    __nv_bfloat16 *w1s, *w2s, *w3s;
    cudaGetSymbolAddress((void**)&Y1,  g_Y1);
    cudaGetSymbolAddress((void**)&Y2,  g_Y2);
    cudaGetSymbolAddress((void**)&bn,  g_bn);
    cudaGetSymbolAddress((void**)&w1s, g_w1s);
    cudaGetSymbolAddress((void**)&w2s, g_w2s);
    cudaGetSymbolAddress((void**)&w3s, g_w3s);
    float* a1 = bn;            float* c1 = bn + COUT3;
    float* a2 = bn + 2*COUT3;  float* c2 = bn + 3*COUT3;
    float* a3 = bn + 4*COUT3;  float* c3 = bn + 5*COUT3;

    // prep
    splitw_kernel<<<COUT1, KP1 >>>(w1, w1s, 131, KP1, 1);
    splitw_kernel<<<COUT2, KP23>>>(w2, w2s, 128, KP23, 0);
    splitw_kernel<<<COUT3, KP23>>>(w3, w3s, 128, KP23, 0);
    {
        dim3 blk(32, 32);
        dim3 grd(NN/32, CC/32, BB);
        transpose_feat_kernel<<<grd, blk>>>(feat);
    }
    ballquery_kernel<<<(BB*MM*32)/256, 256>>>(xyz, indices, out);

    // layer 1: virtual-gathered 144 -> 128, stats fused
    gemm_mma<0,9><<<dim3(NBLK,1), 256>>>(
        nullptr, w1s, 3*KP1, b1, nullptr, nullptr, Y1, xyz, out, COUT1);
    bn_finalize_kernel<<<COUT1, 256>>>(COUT1, g1, e1, a1, c1);

    // layer 2: 128 -> 128 (BN1+ReLU fused in loader)
    gemm_mma<1,8><<<dim3(NBLK,1), 256>>>(
        Y1, w2s, 3*KP23, b2, a1, c1, Y2, nullptr, nullptr, COUT2);
    bn_finalize_kernel<<<COUT2, 256>>>(COUT2, g2, e2, a2, c2);

    // layer 3: 128 -> 256 (BN2+ReLU fused), stats + maxpool fused, no Y3
    gemm_mma<2,8><<<dim3(NBLK,2), 256>>>(
        Y2, w3s, 3*KP23, b3, a2, c2, nullptr, nullptr, nullptr, COUT3);
    bn_finalize_kernel<<<COUT3, 256>>>(COUT3, g3, e3, a3, c3);

    // BN3 + ReLU on pooled maxima
    final_out_kernel<<<NGRP, COUT3>>>(a3, c3, out);
}

// round 6
// speedup vs baseline: 1.7004x; 1.0108x over previous
#include <cuda_runtime.h>
#include <cuda_bf16.h>
#include <math.h>
#include <stdint.h>

// ---------------------------------------------------------------------------
// Problem constants
// ---------------------------------------------------------------------------
#define BB 4
#define NN 16384
#define CC 128
#define MM 1024
#define KK 32
#define RROWS (BB*MM*KK)        // 131072
#define COUT1 128
#define COUT2 128
#define COUT3 256
#define NBLK (RROWS/128)        // 1024 row-tiles
#define NGRP (BB*MM)            // 4096
#define OUT_XYZ_ELEMS (BB*MM*3) // 12288
#define SEGB 4096               // one segment: 128 rows x 32B

// ---------------------------------------------------------------------------
// Scratch (static device globals)
// ---------------------------------------------------------------------------
__device__ float g_featT[(size_t)BB*NN*CC];          // 32 MB (B,N,C)
__device__ int   g_idx[(size_t)BB*MM*KK];            // 512 KB
__device__ float g_Y1[(size_t)RROWS*COUT1];          // 64 MB
__device__ float g_Y2[(size_t)RROWS*COUT2];          // 64 MB
__device__ float g_gmax[(size_t)NGRP*COUT3];         // 4 MB
__device__ unsigned char g_w1s[18*SEGB];             // 9 chunks x {hi,lo} segs
__device__ unsigned char g_w2s[16*SEGB];
__device__ unsigned char g_w3s[2*16*SEGB];           // 2 col-tiles
__device__ float g_part[(size_t)NBLK*2*COUT3];
__device__ float g_bn[6*COUT3];

// ---------------------------------------------------------------------------
// helpers
// ---------------------------------------------------------------------------
__device__ __forceinline__ uint32_t smem_u32(const void* p) {
    uint32_t a;
    asm("{ .reg .u64 t; cvta.to.shared.u64 t, %1; cvt.u32.u64 %0, t; }"
        : "=r"(a) : "l"(p));
    return a;
}
__device__ __forceinline__ uint32_t bf2(float x, float y) {
    __nv_bfloat162 t = __floats2bfloat162_rn(x, y);
    return *reinterpret_cast<uint32_t*>(&t);
}
__device__ __forceinline__ void ldm_x4(uint32_t* r, uint32_t addr) {
    asm volatile("ldmatrix.sync.aligned.m8n8.x4.shared.b16 {%0,%1,%2,%3}, [%4];"
        : "=r"(r[0]), "=r"(r[1]), "=r"(r[2]), "=r"(r[3]) : "r"(addr));
}
__device__ __forceinline__ void mma16816(float* c,
        const uint32_t* a, uint32_t b0, uint32_t b1) {
    asm volatile(
        "mma.sync.aligned.m16n8k16.row.col.f32.bf16.bf16.f32 "
        "{%0,%1,%2,%3}, {%4,%5,%6,%7}, {%8,%9}, {%0,%1,%2,%3};\n"
        : "+f"(c[0]), "+f"(c[1]), "+f"(c[2]), "+f"(c[3])
        : "r"(a[0]), "r"(a[1]), "r"(a[2]), "r"(a[3]), "r"(b0), "r"(b1));
}
#define CP_ASYNC16(dst, src) \
    asm volatile("cp.async.cg.shared.global [%0], [%1], 16;" :: "r"(dst), "l"(src))
#define CP_COMMIT() asm volatile("cp.async.commit_group;" ::: "memory")
#define CP_WAIT0()  asm volatile("cp.async.wait_group 0;" ::: "memory")

// ---------------------------------------------------------------------------
// 1) transpose features (B,C,N) -> (B,N,C)
// ---------------------------------------------------------------------------
__global__ void transpose_feat_kernel(const float* __restrict__ f) {
    __shared__ float tile[32][33];
    int b  = blockIdx.z;
    int n0 = blockIdx.x * 32;
    int c0 = blockIdx.y * 32;
    int tx = threadIdx.x, ty = threadIdx.y;
    tile[ty][tx] = f[((size_t)b*CC + (c0+ty))*NN + (n0+tx)];
    __syncthreads();
    g_featT[((size_t)b*NN + (n0+ty))*CC + (c0+tx)] = tile[tx][ty];
}

// ---------------------------------------------------------------------------
// 2) ball query (proven)
// ---------------------------------------------------------------------------
__global__ void ballquery_kernel(const float* __restrict__ xyz,
                                 const int*   __restrict__ indices,
                                 float*       __restrict__ out_newxyz) {
    int gw   = (blockIdx.x * blockDim.x + threadIdx.x) >> 5;
    int lane = threadIdx.x & 31;
    if (gw >= BB*MM) return;
    int b = gw >> 10;
    const float R2 = (float)(0.4 * 0.4);
    const float* base = xyz + (size_t)b*NN*3;
    int ctr = indices[gw];
    float cx = base[ctr*3+0], cy = base[ctr*3+1], cz = base[ctr*3+2];
    if (lane < 3) out_newxyz[gw*3 + lane] = base[ctr*3+lane];

    int cnt = 0, first = 0;
    int* myidx = g_idx + (size_t)gw*KK;
    for (int j0 = 0; j0 < NN; j0 += 32) {
        int j = j0 + lane;
        float dx = base[j*3+0]-cx, dy = base[j*3+1]-cy, dz = base[j*3+2]-cz;
        float d2 = dx*dx + dy*dy + dz*dz;
        bool within = d2 < R2;
        unsigned mask = __ballot_sync(0xffffffffu, within);
        if (mask) {
            if (cnt == 0) first = j0 + __ffs(mask) - 1;
            int pre = __popc(mask & ((1u << lane) - 1u));
            if (within && (cnt + pre) < KK) myidx[cnt + pre] = j;
            cnt += __popc(mask);
            if (cnt >= KK) break;
        }
    }
    int ce = cnt < KK ? cnt : KK;
    if (lane >= ce) myidx[lane] = first;
}

// ---------------------------------------------------------------------------
// 3) weight split into per-segment smem image:
//    layout per col-tile: [chunk c][seg 0=hi,1=lo][n(128)][16 bf16]
//    perm=1 (layer1): k<128 -> w[:,3+k]; 128..130 -> w[:,k-128]; else 0
// ---------------------------------------------------------------------------
__global__ void splitw_kernel(const float* __restrict__ w,
                              unsigned char* __restrict__ out,
                              int Cin, int nSeg, int perm) {
    int o = blockIdx.x, k = threadIdx.x;
    int wt = o >> 7, n = o & 127;
    float v;
    if (perm) {
        if (k < 128)      v = w[o*Cin + 3 + k];
        else if (k < 131) v = w[o*Cin + (k - 128)];
        else              v = 0.f;
    } else {
        v = (k < Cin) ? w[o*Cin + k] : 0.f;
    }
    __nv_bfloat16 h = __float2bfloat16_rn(v);
    __nv_bfloat16 l = __float2bfloat16_rn(v - __bfloat162float(h));
    int c = k >> 4, kk = k & 15;
    unsigned char* base = out + (size_t)wt * nSeg * SEGB;
    *(__nv_bfloat16*)(base + ((size_t)(2*c+0)*128 + n)*32 + kk*2) = h;
    *(__nv_bfloat16*)(base + ((size_t)(2*c+1)*128 + n)*32 + kk*2) = l;
}

// ---------------------------------------------------------------------------
// Persistent ldmatrix/mma fused GEMM.  Y = act(A) @ W^T + bias (+stats/max)
//   MODE 0: A = virtual gathered X1 (featT + dxyz), K=144 (9 chunks) -> Y1
//   MODE 1: A = Y1, act=relu(bn).  K=128.                            -> Y2
//   MODE 2: A = Y2, act=relu(bn).  stats + K-group max, no Y.
// Block 128x128, 256 thr (8 warps: wm 0..3 x wn 0..1, warp tile 32x64).
// Split precision: A,W stored {hi,lo}; products hi*hi + hi*lo + lo*hi.
// Whole K resident in smem; A fp32 stage cp.async-prefetched per tile.
// ---------------------------------------------------------------------------
template<int MODE>
__global__ __launch_bounds__(256, 1)
void gemm_lm(const float* __restrict__ A,
             const unsigned char* __restrict__ Wt,
             const float* __restrict__ bias,
             const float* __restrict__ bn_a, const float* __restrict__ bn_c,
             float* __restrict__ Y,
             const float* __restrict__ xyz, const float* __restrict__ newxyz) {
    constexpr int NCH   = (MODE == 0) ? 9 : 8;
    constexpr int NSEG  = 2 * NCH;
    constexpr int COUTT = (MODE == 2) ? 256 : 128;

    extern __shared__ unsigned char dsm[];
    unsigned char* Asm  = dsm;                    // NSEG*SEGB
    unsigned char* Wsm  = dsm + NSEG*SEGB;        // NSEG*SEGB
    float*         stg  = (float*)(dsm + 2*NSEG*SEGB);  // 128 rows x 128 f32

    __shared__ float s_bias[128];
    __shared__ float s_bna[128], s_bnc[128];
    __shared__ float red_s[4][128], red_q[4][128], red_m[4][128];

    int tid  = threadIdx.x;
    int lane = tid & 31, warp = tid >> 5;
    int wm = warp >> 1, wn = warp & 1;
    int colTile = blockIdx.y * 128;

    uint32_t asm_a = smem_u32(Asm);
    uint32_t wsm_a = smem_u32(Wsm);
    uint32_t stg_a = smem_u32(stg);

    if (tid < 128) {
        s_bias[tid] = bias[colTile + tid];
        if (MODE != 0) { s_bna[tid] = bn_a[tid]; s_bnc[tid] = bn_c[tid]; }
    }

    int row  = tid >> 1;      // loader/transform row 0..127
    int half = tid & 1;       // chunk parity

    // ---- per-thread A stage prefetch: chunks c = half, half+2, ... (<8) ----
    auto prefetch = [&](int t) {
        int rg = t*128 + row;
        const float* src;
        if (MODE == 0) {
            int jj = g_idx[rg];
            int bb = rg >> 15;
            src = g_featT + ((size_t)bb*NN + jj)*CC;
        } else {
            src = A + (size_t)rg*128;
        }
        #pragma unroll
        for (int c = 0; c < 8; c++) {
            if ((c & 1) != half) continue;
            uint32_t dst = stg_a + (uint32_t)(row*128 + c*16)*4;
            #pragma unroll
            for (int i = 0; i < 4; i++)
                CP_ASYNC16(dst + i*16, src + c*16 + i*4);
        }
        CP_COMMIT();
    };

    // ---- W tile -> smem (once) ----
    {
        const unsigned char* wsrc = Wt + (size_t)blockIdx.y * NSEG * SEGB;
        for (int i = tid; i < NSEG*256; i += 256)
            CP_ASYNC16(wsm_a + i*16, wsrc + (size_t)i*16);
    }
    prefetch(blockIdx.x);   // commits W + first stage in one group

    // ---- fragment address offsets (within a 4KB segment) ----
    uint32_t aoff = (uint32_t)((wm*32 + (lane & 7) + ((lane >> 3) & 1)*8)*32
                               + ((lane >> 4) & 1)*16);
    uint32_t boff = (uint32_t)((wn*64 + (lane & 7) + ((lane >> 4) & 1)*8)*32
                               + ((lane >> 3) & 1)*16);
    int gg = lane >> 2, tq = lane & 3;

    for (int t = blockIdx.x; t < NBLK; t += gridDim.x) {
        CP_WAIT0();          // own stage rows (and W, first iter) arrived
        __syncthreads();     // everyone done reading Asm of previous tile

        // ---- transform: stage fp32 -> BN/ReLU -> {hi,lo} bf16 segs ----
        for (int c = half; c < NCH; c += 2) {
            float v[16];
            if (MODE == 0 && c == 8) {
                int rg = t*128 + row;
                int jj = g_idx[rg];
                int bb = rg >> 15;
                const float* pp = xyz    + ((size_t)bb*NN + jj)*3;
                const float* cq = newxyz + (size_t)(rg >> 5)*3;
                v[0] = pp[0]-cq[0]; v[1] = pp[1]-cq[1]; v[2] = pp[2]-cq[2];
                #pragma unroll
                for (int j = 3; j < 16; j++) v[j] = 0.f;
            } else {
                const float* sr = stg + row*128 + c*16;
                #pragma unroll
                for (int j = 0; j < 16; j += 4) {
                    float4 f = *(const float4*)(sr + j);
                    v[j] = f.x; v[j+1] = f.y; v[j+2] = f.z; v[j+3] = f.w;
                }
                if (MODE != 0) {
                    #pragma unroll
                    for (int j = 0; j < 16; j++) {
                        int kb = c*16 + j;
                        v[j] = fmaxf(fmaf(v[j], s_bna[kb], s_bnc[kb]), 0.f);
                    }
                }
            }
            uint32_t hq[8], lq[8];
            #pragma unroll
            for (int p = 0; p < 8; p++) {
                float h0 = __bfloat162float(__float2bfloat16_rn(v[2*p]));
                float h1 = __bfloat162float(__float2bfloat16_rn(v[2*p+1]));
                hq[p] = bf2(h0, h1);
                lq[p] = bf2(v[2*p] - h0, v[2*p+1] - h1);
            }
            unsigned char* ph = Asm + (size_t)(2*c)*SEGB + row*32;
            *(uint4*)(ph)            = *(uint4*)&hq[0];
            *(uint4*)(ph + 16)       = *(uint4*)&hq[4];
            *(uint4*)(ph + SEGB)     = *(uint4*)&lq[0];
            *(uint4*)(ph + SEGB+16)  = *(uint4*)&lq[4];
        }
        __syncthreads();

        // ---- prefetch next tile's stage while MMAs run ----
        int tn = t + gridDim.x;
        if (tn < NBLK) prefetch(tn);

        // ---- mma mainloop: whole K, no barriers ----
        float acc[2][8][4];
        #pragma unroll
        for (int mf = 0; mf < 2; mf++)
            #pragma unroll
            for (int nf = 0; nf < 8; nf++)
                #pragma unroll
                for (int r2 = 0; r2 < 4; r2++) acc[mf][nf][r2] = 0.f;

        #pragma unroll
        for (int c = 0; c < NCH; c++) {
            uint32_t segH = asm_a + (uint32_t)(2*c)*SEGB;
            uint32_t segL = segH + SEGB;
            uint32_t ah[2][4], al[2][4];
            ldm_x4(ah[0], segH + aoff);
            ldm_x4(ah[1], segH + aoff + 512);
            ldm_x4(al[0], segL + aoff);
            ldm_x4(al[1], segL + aoff + 512);
            uint32_t bh[8][2], bl[8][2];
            #pragma unroll
            for (int j = 0; j < 4; j++) {
                uint32_t r4[4];
                ldm_x4(r4, wsm_a + (uint32_t)(2*c)*SEGB + boff + j*512);
                bh[2*j][0] = r4[0]; bh[2*j][1] = r4[1];
                bh[2*j+1][0] = r4[2]; bh[2*j+1][1] = r4[3];
                ldm_x4(r4, wsm_a + (uint32_t)(2*c+1)*SEGB + boff + j*512);
                bl[2*j][0] = r4[0]; bl[2*j][1] = r4[1];
                bl[2*j+1][0] = r4[2]; bl[2*j+1][1] = r4[3];
            }
            #pragma unroll
            for (int nf = 0; nf < 8; nf++) {
                mma16816(acc[0][nf], ah[0], bh[nf][0], bh[nf][1]);
                mma16816(acc[1][nf], ah[1], bh[nf][0], bh[nf][1]);
                mma16816(acc[0][nf], ah[0], bl[nf][0], bl[nf][1]);
                mma16816(acc[1][nf], ah[1], bl[nf][0], bl[nf][1]);
                mma16816(acc[0][nf], al[0], bh[nf][0], bh[nf][1]);
                mma16816(acc[1][nf], al[1], bh[nf][0], bh[nf][1]);
            }
        }

        // ---- epilogue: bias, Y write, stats, (max) ----
        float bs[8][2];
        #pragma unroll
        for (int nf = 0; nf < 8; nf++) {
            int col = wn*64 + nf*8 + 2*tq;
            bs[nf][0] = s_bias[col];
            bs[nf][1] = s_bias[col+1];
        }
        float s16[8][2], q16[8][2], m16[8][2];
        #pragma unroll
        for (int nf = 0; nf < 8; nf++)
            #pragma unroll
            for (int e = 0; e < 2; e++) { s16[nf][e]=0.f; q16[nf][e]=0.f; m16[nf][e]=-3.4e38f; }

        #pragma unroll
        for (int mf = 0; mf < 2; mf++) {
            #pragma unroll
            for (int nf = 0; nf < 8; nf++) {
                float v0 = acc[mf][nf][0] + bs[nf][0];
                float v1 = acc[mf][nf][1] + bs[nf][1];
                float v2 = acc[mf][nf][2] + bs[nf][0];
                float v3 = acc[mf][nf][3] + bs[nf][1];
                s16[nf][0] += v0 + v2;  s16[nf][1] += v1 + v3;
                q16[nf][0] = fmaf(v0,v0,fmaf(v2,v2,q16[nf][0]));
                q16[nf][1] = fmaf(v1,v1,fmaf(v3,v3,q16[nf][1]));
                m16[nf][0] = fmaxf(m16[nf][0], fmaxf(v0, v2));
                m16[nf][1] = fmaxf(m16[nf][1], fmaxf(v1, v3));
                if (MODE != 2) {
                    int r0 = t*128 + wm*32 + mf*16 + gg;
                    int cb = colTile + wn*64 + nf*8 + 2*tq;
                    *(float2*)(Y + (size_t)r0*COUTT + cb)     = make_float2(v0, v1);
                    *(float2*)(Y + (size_t)(r0+8)*COUTT + cb) = make_float2(v2, v3);
                }
            }
        }

        #pragma unroll
        for (int off = 4; off <= 16; off <<= 1) {
            #pragma unroll
            for (int nf = 0; nf < 8; nf++)
                #pragma unroll
                for (int e = 0; e < 2; e++) {
                    s16[nf][e] += __shfl_xor_sync(0xffffffffu, s16[nf][e], off);
                    q16[nf][e] += __shfl_xor_sync(0xffffffffu, q16[nf][e], off);
                    m16[nf][e] = fmaxf(m16[nf][e], __shfl_xor_sync(0xffffffffu, m16[nf][e], off));
                }
        }
        if (gg == 0) {
            #pragma unroll
            for (int nf = 0; nf < 8; nf++)
                #pragma unroll
                for (int e = 0; e < 2; e++) {
                    int cl = wn*64 + nf*8 + 2*tq + e;
                    red_s[wm][cl] = s16[nf][e];
                    red_q[wm][cl] = q16[nf][e];
                    if (MODE == 2) red_m[wm][cl] = m16[nf][e];
                }
        }
        __syncthreads();

        if (tid < 128) {
            int c = tid;
            float ss = red_s[0][c] + red_s[1][c] + red_s[2][c] + red_s[3][c];
            float qq = red_q[0][c] + red_q[1][c] + red_q[2][c] + red_q[3][c];
            size_t pb = (size_t)t * (2*COUTT);
            g_part[pb + colTile + c]         = ss;
            g_part[pb + COUTT + colTile + c] = qq;
            if (MODE == 2) {
                #pragma unroll
                for (int wmi = 0; wmi < 4; wmi++)
                    g_gmax[((size_t)(t*4 + wmi))*COUT3 + colTile + c] = red_m[wmi][c];
            }
        }
    }
}

// ---------------------------------------------------------------------------
// BN finalize (fixed-order, deterministic)
// ---------------------------------------------------------------------------
__global__ void bn_finalize_kernel(int C,
                                   const float* __restrict__ g,
                                   const float* __restrict__ beta,
                                   float* __restrict__ bn_a,
                                   float* __restrict__ bn_c) {
    __shared__ float sh_s[256], sh_q[256];
    int ch = blockIdx.x;
    int t  = threadIdx.x;
    float s = 0.f, q = 0.f;
    for (int b = t; b < NBLK; b += 256) {
        size_t base = (size_t)b * (2*C);
        s += g_part[base + ch];
        q += g_part[base + C + ch];
    }
    sh_s[t] = s; sh_q[t] = q;
    __syncthreads();
    for (int off = 128; off > 0; off >>= 1) {
        if (t < off) { sh_s[t] += sh_s[t+off]; sh_q[t] += sh_q[t+off]; }
        __syncthreads();
    }
    if (t == 0) {
        const float invR = 1.0f / (float)RROWS;
        float mu  = sh_s[0] * invR;
        float var = sh_q[0] * invR - mu*mu;
        float a = g[ch] * rsqrtf(var + 1e-5f);
        bn_a[ch] = a;
        bn_c[ch] = beta[ch] - a*mu;
    }
}

// ---------------------------------------------------------------------------
// Final: relu(a3*gmax + c3) -> out (a3>0 so BN+relu commute with max)
// ---------------------------------------------------------------------------
__global__ void final_out_kernel(const float* __restrict__ bn_a,
                                 const float* __restrict__ bn_c,
                                 float* __restrict__ out) {
    int grp = blockIdx.x;
    int co  = threadIdx.x;
    float v = g_gmax[(size_t)grp*COUT3 + co];
    float r = fmaxf(fmaf(bn_a[co], v, bn_c[co]), 0.f);
    int b = grp >> 10, m = grp & 1023;
    out[OUT_XYZ_ELEMS + ((size_t)(b*COUT3 + co))*MM + m] = r;
}

// ---------------------------------------------------------------------------
// host launcher
// ---------------------------------------------------------------------------
extern "C" void kernel_launch(void* const* d_in, const int* in_sizes, int n_in,
                              void* d_out, int out_size) {
    const float* xyz     = (const float*)d_in[0];
    const float* feat    = (const float*)d_in[1];
    const int*   indices = (const int*)  d_in[2];
    const float* w1 = (const float*)d_in[3];
    const float* b1 = (const float*)d_in[4];
    const float* g1 = (const float*)d_in[5];
    const float* e1 = (const float*)d_in[6];
    const float* w2 = (const float*)d_in[7];
    const float* b2 = (const float*)d_in[8];
    const float* g2 = (const float*)d_in[9];
    const float* e2 = (const float*)d_in[10];
    const float* w3 = (const float*)d_in[11];
    const float* b3 = (const float*)d_in[12];
    const float* g3 = (const float*)d_in[13];
    const float* e3 = (const float*)d_in[14];
    float* out = (float*)d_out;

    float *Y1, *Y2, *bn;
    unsigned char *w1s, *w2s, *w3s;
    cudaGetSymbolAddress((void**)&Y1,  g_Y1);
    cudaGetSymbolAddress((void**)&Y2,  g_Y2);
    cudaGetSymbolAddress((void**)&bn,  g_bn);
    cudaGetSymbolAddress((void**)&w1s, g_w1s);
    cudaGetSymbolAddress((void**)&w2s, g_w2s);
    cudaGetSymbolAddress((void**)&w3s, g_w3s);
    float* a1 = bn;            float* c1 = bn + COUT3;
    float* a2 = bn + 2*COUT3;  float* c2 = bn + 3*COUT3;
    float* a3 = bn + 4*COUT3;  float* c3 = bn + 5*COUT3;

    int smem1  = 2*18*SEGB + 128*128*4;   // 212992
    int smem23 = 2*16*SEGB + 128*128*4;   // 196608
    cudaFuncSetAttribute(gemm_lm<0>, cudaFuncAttributeMaxDynamicSharedMemorySize, smem1);
    cudaFuncSetAttribute(gemm_lm<1>, cudaFuncAttributeMaxDynamicSharedMemorySize, smem23);
    cudaFuncSetAttribute(gemm_lm<2>, cudaFuncAttributeMaxDynamicSharedMemorySize, smem23);

    // prep
    splitw_kernel<<<COUT1, 144>>>(w1, w1s, 131, 18, 1);
    splitw_kernel<<<COUT2, 128>>>(w2, w2s, 128, 16, 0);
    splitw_kernel<<<COUT3, 128>>>(w3, w3s, 128, 16, 0);
    {
        dim3 blk(32, 32);
        dim3 grd(NN/32, CC/32, BB);
        transpose_feat_kernel<<<grd, blk>>>(feat);
    }
    ballquery_kernel<<<(BB*MM*32)/256, 256>>>(xyz, indices, out);

    // layer 1: virtual-gathered 144 -> 128, stats fused
    gemm_lm<0><<<dim3(148,1), 256, smem1>>>(nullptr, w1s, b1, nullptr, nullptr,
                                            Y1, xyz, out);
    bn_finalize_kernel<<<COUT1, 256>>>(COUT1, g1, e1, a1, c1);

    // layer 2: 128 -> 128 (BN1+ReLU fused into A-transform)
    gemm_lm<1><<<dim3(148,1), 256, smem23>>>(Y1, w2s, b2, a1, c1,
                                             Y2, nullptr, nullptr);
    bn_finalize_kernel<<<COUT2, 256>>>(COUT2, g2, e2, a2, c2);

    // layer 3: 128 -> 256 (BN2+ReLU fused), stats + maxpool fused, no Y3
    gemm_lm<2><<<dim3(74,2), 256, smem23>>>(Y2, w3s, b3, a2, c2,
                                            nullptr, nullptr, nullptr);
    bn_finalize_kernel<<<COUT3, 256>>>(COUT3, g3, e3, a3, c3);

    // BN3 + ReLU on pooled maxima
    final_out_kernel<<<NGRP, COUT3>>>(a3, c3, out);
}

// round 7
// speedup vs baseline: 2.0804x; 1.2235x over previous
#include <cuda_runtime.h>
#include <cuda_bf16.h>
#include <math.h>
#include <stdint.h>

// ---------------------------------------------------------------------------
// Problem constants
// ---------------------------------------------------------------------------
#define BB 4
#define NN 16384
#define CC 128
#define MM 1024
#define KK 32
#define RROWS (BB*MM*KK)        // 131072
#define COUT1 128
#define COUT2 128
#define COUT3 256
#define NBLK (RROWS/128)        // 1024 row-tiles
#define NGRP (BB*MM)            // 4096
#define OUT_XYZ_ELEMS (BB*MM*3) // 12288
#define SEGB 4096               // one segment: 128 rows x 32B

// ---------------------------------------------------------------------------
// Scratch (static device globals)
// ---------------------------------------------------------------------------
__device__ float g_featT[(size_t)BB*NN*CC];          // 32 MB (B,N,C)
__device__ int   g_idx[(size_t)BB*MM*KK];            // 512 KB
__device__ float g_Y1[(size_t)RROWS*COUT1];          // 64 MB
__device__ float g_Y2[(size_t)RROWS*COUT2];          // 64 MB
__device__ float g_gmax[(size_t)NGRP*COUT3];         // 4 MB
__device__ unsigned char g_w1s[18*SEGB];             // 9 chunks x {hi,lo} segs
__device__ unsigned char g_w2s[16*SEGB];
__device__ unsigned char g_w3s[2*16*SEGB];           // 2 col-tiles
__device__ float g_part[(size_t)NBLK*2*COUT3];
__device__ float g_bn[6*COUT3];

// ---------------------------------------------------------------------------
// helpers
// ---------------------------------------------------------------------------
__device__ __forceinline__ uint32_t smem_u32(const void* p) {
    uint32_t a;
    asm("{ .reg .u64 t; cvta.to.shared.u64 t, %1; cvt.u32.u64 %0, t; }"
        : "=r"(a) : "l"(p));
    return a;
}
__device__ __forceinline__ void ldm_x4(uint32_t* r, uint32_t addr) {
    asm volatile("ldmatrix.sync.aligned.m8n8.x4.shared.b16 {%0,%1,%2,%3}, [%4];"
        : "=r"(r[0]), "=r"(r[1]), "=r"(r[2]), "=r"(r[3]) : "r"(addr));
}
__device__ __forceinline__ void mma16816(float* c,
        const uint32_t* a, uint32_t b0, uint32_t b1) {
    asm volatile(
        "mma.sync.aligned.m16n8k16.row.col.f32.bf16.bf16.f32 "
        "{%0,%1,%2,%3}, {%4,%5,%6,%7}, {%8,%9}, {%0,%1,%2,%3};\n"
        : "+f"(c[0]), "+f"(c[1]), "+f"(c[2]), "+f"(c[3])
        : "r"(a[0]), "r"(a[1]), "r"(a[2]), "r"(a[3]), "r"(b0), "r"(b1));
}
#define CP_ASYNC16(dst, src) \
    asm volatile("cp.async.cg.shared.global [%0], [%1], 16;" :: "r"(dst), "l"(src))
#define CP_COMMIT() asm volatile("cp.async.commit_group;" ::: "memory")
#define CP_WAIT0()  asm volatile("cp.async.wait_group 0;" ::: "memory")

// ---------------------------------------------------------------------------
// 1) transpose features (B,C,N) -> (B,N,C).  256 thr, float4 both directions.
// ---------------------------------------------------------------------------
__global__ void transpose_feat_kernel(const float* __restrict__ f) {
    __shared__ __align__(16) float tile[32][132];
    int b  = blockIdx.z;
    int n0 = blockIdx.x * 128;
    int c0 = blockIdx.y * 32;
    int tx = threadIdx.x, ty = threadIdx.y;   // (32, 8)
    #pragma unroll
    for (int i = 0; i < 4; i++) {
        int c = ty*4 + i;
        float4 v = *(const float4*)(f + ((size_t)b*CC + c0 + c)*NN + n0 + tx*4);
        *(float4*)&tile[c][tx*4] = v;
    }
    __syncthreads();
    int t = ty*32 + tx;
    int n = t & 127, cg = t >> 7;
    #pragma unroll
    for (int i = 0; i < 4; i++) {
        int c = cg*16 + i*4;
        float4 v = make_float4(tile[c][n], tile[c+1][n], tile[c+2][n], tile[c+3][n]);
        *(float4*)(g_featT + ((size_t)b*NN + n0 + n)*CC + c0 + c) = v;
    }
}

// ---------------------------------------------------------------------------
// 2) ball query: warp per query, 64 points/iteration (2 per lane).
//    Writes new_xyz directly into d_out[0:12288).
// ---------------------------------------------------------------------------
__global__ void ballquery_kernel(const float* __restrict__ xyz,
                                 const int*   __restrict__ indices,
                                 float*       __restrict__ out_newxyz) {
    int gw   = (blockIdx.x * blockDim.x + threadIdx.x) >> 5;
    int lane = threadIdx.x & 31;
    if (gw >= BB*MM) return;
    int b = gw >> 10;
    const float R2 = (float)(0.4 * 0.4);
    const float* base = xyz + (size_t)b*NN*3;
    int ctr = indices[gw];
    float cx = base[ctr*3+0], cy = base[ctr*3+1], cz = base[ctr*3+2];
    if (lane < 3) out_newxyz[gw*3 + lane] = base[ctr*3+lane];

    unsigned lt = (1u << lane) - 1u;
    int cnt = 0, first = 0;
    int* myidx = g_idx + (size_t)gw*KK;
    for (int j0 = 0; j0 < NN; j0 += 64) {
        int ja = j0 + lane, jb = j0 + 32 + lane;
        float dxa = base[ja*3+0]-cx, dya = base[ja*3+1]-cy, dza = base[ja*3+2]-cz;
        float dxb = base[jb*3+0]-cx, dyb = base[jb*3+1]-cy, dzb = base[jb*3+2]-cz;
        bool wa = (dxa*dxa + dya*dya + dza*dza) < R2;
        bool wb = (dxb*dxb + dyb*dyb + dzb*dzb) < R2;
        unsigned m1 = __ballot_sync(0xffffffffu, wa);
        unsigned m2 = __ballot_sync(0xffffffffu, wb);
        if (m1 | m2) {
            if (cnt == 0)
                first = m1 ? (j0 + __ffs(m1) - 1) : (j0 + 32 + __ffs(m2) - 1);
            int c1 = __popc(m1);
            int p1 = __popc(m1 & lt);
            if (wa && (cnt + p1) < KK) myidx[cnt + p1] = ja;
            int p2 = __popc(m2 & lt);
            if (wb && (cnt + c1 + p2) < KK) myidx[cnt + c1 + p2] = jb;
            cnt += c1 + __popc(m2);
            if (cnt >= KK) break;
        }
    }
    int ce = cnt < KK ? cnt : KK;
    if (lane >= ce) myidx[lane] = first;
}

// ---------------------------------------------------------------------------
// 3) weight split into per-segment smem image:
//    layout per col-tile: [chunk c][seg 0=hi,1=lo][n(128)][16 bf16]
//    perm=1 (layer1): k<128 -> w[:,3+k]; 128..130 -> w[:,k-128]; else 0
// ---------------------------------------------------------------------------
__global__ void splitw_kernel(const float* __restrict__ w,
                              unsigned char* __restrict__ out,
                              int Cin, int nSeg, int perm) {
    int o = blockIdx.x, k = threadIdx.x;
    int wt = o >> 7, n = o & 127;
    float v;
    if (perm) {
        if (k < 128)      v = w[o*Cin + 3 + k];
        else if (k < 131) v = w[o*Cin + (k - 128)];
        else              v = 0.f;
    } else {
        v = (k < Cin) ? w[o*Cin + k] : 0.f;
    }
    __nv_bfloat16 h = __float2bfloat16_rn(v);
    __nv_bfloat16 l = __float2bfloat16_rn(v - __bfloat162float(h));
    int c = k >> 4, kk = k & 15;
    unsigned char* base = out + (size_t)wt * nSeg * SEGB;
    *(__nv_bfloat16*)(base + ((size_t)(2*c+0)*128 + n)*32 + kk*2) = h;
    *(__nv_bfloat16*)(base + ((size_t)(2*c+1)*128 + n)*32 + kk*2) = l;
}

// ---------------------------------------------------------------------------
// Persistent ldmatrix/mma fused GEMM.  Y = act(A) @ W^T + bias (+stats/max)
//   MODE 0: A = virtual gathered X1 (featT + dxyz), K=144 (9 chunks) -> Y1
//   MODE 1: A = Y1, act=relu(bn).  K=128.                            -> Y2
//   MODE 2: A = Y2, act=relu(bn).  stats + K-group max, no Y.
// Block 128x128, 256 thr (8 warps: wm 0..3 x wn 0..1, warp tile 32x64).
// Split precision: A,W stored {hi,lo}; products hi*hi + hi*lo + lo*hi.
// A split uses integer round+mask+PRMT (no F2FP on the critical path).
// ---------------------------------------------------------------------------
template<int MODE>
__global__ __launch_bounds__(256, 1)
void gemm_lm(const float* __restrict__ A,
             const unsigned char* __restrict__ Wt,
             const float* __restrict__ bias,
             const float* __restrict__ bn_a, const float* __restrict__ bn_c,
             float* __restrict__ Y,
             const float* __restrict__ xyz, const float* __restrict__ newxyz) {
    constexpr int NCH   = (MODE == 0) ? 9 : 8;
    constexpr int NSEG  = 2 * NCH;
    constexpr int COUTT = (MODE == 2) ? 256 : 128;

    extern __shared__ unsigned char dsm[];
    unsigned char* Asm  = dsm;                    // NSEG*SEGB
    unsigned char* Wsm  = dsm + NSEG*SEGB;        // NSEG*SEGB
    float*         stg  = (float*)(dsm + 2*NSEG*SEGB);  // 128 rows x 128 f32

    __shared__ float s_bias[128];
    __shared__ float s_bna[128], s_bnc[128];
    __shared__ float red_s[4][128], red_q[4][128], red_m[4][128];

    int tid  = threadIdx.x;
    int lane = tid & 31, warp = tid >> 5;
    int wm = warp >> 1, wn = warp & 1;
    int colTile = blockIdx.y * 128;

    uint32_t asm_a = smem_u32(Asm);
    uint32_t wsm_a = smem_u32(Wsm);
    uint32_t stg_a = smem_u32(stg);

    if (tid < 128) {
        s_bias[tid] = bias[colTile + tid];
        if (MODE != 0) { s_bna[tid] = bn_a[tid]; s_bnc[tid] = bn_c[tid]; }
    }

    int row  = tid >> 1;      // loader/transform row 0..127
    int half = tid & 1;       // chunk parity

    // ---- per-thread A stage prefetch: chunks c = half, half+2, ... (<8) ----
    auto prefetch = [&](int t) {
        int rg = t*128 + row;
        const float* src;
        if (MODE == 0) {
            int jj = g_idx[rg];
            int bb = rg >> 15;
            src = g_featT + ((size_t)bb*NN + jj)*CC;
        } else {
            src = A + (size_t)rg*128;
        }
        #pragma unroll
        for (int c = 0; c < 8; c++) {
            if ((c & 1) != half) continue;
            uint32_t dst = stg_a + (uint32_t)(row*128 + c*16)*4;
            #pragma unroll
            for (int i = 0; i < 4; i++)
                CP_ASYNC16(dst + i*16, src + c*16 + i*4);
        }
        CP_COMMIT();
    };

    // ---- W tile -> smem (once) ----
    {
        const unsigned char* wsrc = Wt + (size_t)blockIdx.y * NSEG * SEGB;
        for (int i = tid; i < NSEG*256; i += 256)
            CP_ASYNC16(wsm_a + i*16, wsrc + (size_t)i*16);
    }
    prefetch(blockIdx.x);   // commits W + first stage in one group

    // ---- fragment address offsets (within a 4KB segment) ----
    uint32_t aoff = (uint32_t)((wm*32 + (lane & 7) + ((lane >> 3) & 1)*8)*32
                               + ((lane >> 4) & 1)*16);
    uint32_t boff = (uint32_t)((wn*64 + (lane & 7) + ((lane >> 4) & 1)*8)*32
                               + ((lane >> 3) & 1)*16);
    int gg = lane >> 2, tq = lane & 3;

    for (int t = blockIdx.x; t < NBLK; t += gridDim.x) {
        CP_WAIT0();          // own stage rows (and W, first iter) arrived
        __syncthreads();     // everyone done reading Asm of previous tile

        // ---- transform: stage fp32 -> BN/ReLU -> {hi,lo} bf16 via ALU ----
        for (int c = half; c < NCH; c += 2) {
            float v[16];
            if (MODE == 0 && c == 8) {
                int rg = t*128 + row;
                int jj = g_idx[rg];
                int bb = rg >> 15;
                const float* pp = xyz    + ((size_t)bb*NN + jj)*3;
                const float* cq = newxyz + (size_t)(rg >> 5)*3;
                v[0] = pp[0]-cq[0]; v[1] = pp[1]-cq[1]; v[2] = pp[2]-cq[2];
                #pragma unroll
                for (int j = 3; j < 16; j++) v[j] = 0.f;
            } else {
                const float* sr = stg + row*128 + c*16;
                #pragma unroll
                for (int j = 0; j < 16; j += 4) {
                    float4 f = *(const float4*)(sr + j);
                    v[j] = f.x; v[j+1] = f.y; v[j+2] = f.z; v[j+3] = f.w;
                }
                if (MODE != 0) {
                    #pragma unroll
                    for (int j = 0; j < 16; j++) {
                        int kb = c*16 + j;
                        v[j] = fmaxf(fmaf(v[j], s_bna[kb], s_bnc[kb]), 0.f);
                    }
                }
            }
            uint32_t hq[8], lq[8];
            #pragma unroll
            for (int p = 0; p < 8; p++) {
                uint32_t t0 = __float_as_uint(v[2*p])   + 0x8000u;
                uint32_t t1 = __float_as_uint(v[2*p+1]) + 0x8000u;
                float h0 = __uint_as_float(t0 & 0xFFFF0000u);
                float h1 = __uint_as_float(t1 & 0xFFFF0000u);
                hq[p] = __byte_perm(t0, t1, 0x7632);
                uint32_t l0 = __float_as_uint(v[2*p]   - h0) + 0x8000u;
                uint32_t l1 = __float_as_uint(v[2*p+1] - h1) + 0x8000u;
                lq[p] = __byte_perm(l0, l1, 0x7632);
            }
            unsigned char* ph = Asm + (size_t)(2*c)*SEGB + row*32;
            *(uint4*)(ph)            = *(uint4*)&hq[0];
            *(uint4*)(ph + 16)       = *(uint4*)&hq[4];
            *(uint4*)(ph + SEGB)     = *(uint4*)&lq[0];
            *(uint4*)(ph + SEGB+16)  = *(uint4*)&lq[4];
        }
        __syncthreads();

        // ---- prefetch next tile's stage while MMAs run ----
        int tn = t + gridDim.x;
        if (tn < NBLK) prefetch(tn);

        // ---- mma mainloop: whole K, no barriers ----
        float acc[2][8][4];
        #pragma unroll
        for (int mf = 0; mf < 2; mf++)
            #pragma unroll
            for (int nf = 0; nf < 8; nf++)
                #pragma unroll
                for (int r2 = 0; r2 < 4; r2++) acc[mf][nf][r2] = 0.f;

        #pragma unroll
        for (int c = 0; c < NCH; c++) {
            uint32_t segH = asm_a + (uint32_t)(2*c)*SEGB;
            uint32_t segL = segH + SEGB;
            uint32_t ah[2][4], al[2][4];
            ldm_x4(ah[0], segH + aoff);
            ldm_x4(ah[1], segH + aoff + 512);
            ldm_x4(al[0], segL + aoff);
            ldm_x4(al[1], segL + aoff + 512);
            uint32_t bh[8][2], bl[8][2];
            #pragma unroll
            for (int j = 0; j < 4; j++) {
                uint32_t r4[4];
                ldm_x4(r4, wsm_a + (uint32_t)(2*c)*SEGB + boff + j*512);
                bh[2*j][0] = r4[0]; bh[2*j][1] = r4[1];
                bh[2*j+1][0] = r4[2]; bh[2*j+1][1] = r4[3];
                ldm_x4(r4, wsm_a + (uint32_t)(2*c+1)*SEGB + boff + j*512);
                bl[2*j][0] = r4[0]; bl[2*j][1] = r4[1];
                bl[2*j+1][0] = r4[2]; bl[2*j+1][1] = r4[3];
            }
            #pragma unroll
            for (int nf = 0; nf < 8; nf++) {
                mma16816(acc[0][nf], ah[0], bh[nf][0], bh[nf][1]);
                mma16816(acc[1][nf], ah[1], bh[nf][0], bh[nf][1]);
                mma16816(acc[0][nf], ah[0], bl[nf][0], bl[nf][1]);
                mma16816(acc[1][nf], ah[1], bl[nf][0], bl[nf][1]);
                mma16816(acc[0][nf], al[0], bh[nf][0], bh[nf][1]);
                mma16816(acc[1][nf], al[1], bh[nf][0], bh[nf][1]);
            }
        }

        // ---- epilogue: bias, Y write, stats, (max) ----
        float bs[8][2];
        #pragma unroll
        for (int nf = 0; nf < 8; nf++) {
            int col = wn*64 + nf*8 + 2*tq;
            bs[nf][0] = s_bias[col];
            bs[nf][1] = s_bias[col+1];
        }
        float s16[8][2], q16[8][2], m16[8][2];
        #pragma unroll
        for (int nf = 0; nf < 8; nf++)
            #pragma unroll
            for (int e = 0; e < 2; e++) { s16[nf][e]=0.f; q16[nf][e]=0.f; m16[nf][e]=-3.4e38f; }

        #pragma unroll
        for (int mf = 0; mf < 2; mf++) {
            #pragma unroll
            for (int nf = 0; nf < 8; nf++) {
                float v0 = acc[mf][nf][0] + bs[nf][0];
                float v1 = acc[mf][nf][1] + bs[nf][1];
                float v2 = acc[mf][nf][2] + bs[nf][0];
                float v3 = acc[mf][nf][3] + bs[nf][1];
                s16[nf][0] += v0 + v2;  s16[nf][1] += v1 + v3;
                q16[nf][0] = fmaf(v0,v0,fmaf(v2,v2,q16[nf][0]));
                q16[nf][1] = fmaf(v1,v1,fmaf(v3,v3,q16[nf][1]));
                m16[nf][0] = fmaxf(m16[nf][0], fmaxf(v0, v2));
                m16[nf][1] = fmaxf(m16[nf][1], fmaxf(v1, v3));
                if (MODE != 2) {
                    int r0 = t*128 + wm*32 + mf*16 + gg;
                    int cb = colTile + wn*64 + nf*8 + 2*tq;
                    *(float2*)(Y + (size_t)r0*COUTT + cb)     = make_float2(v0, v1);
                    *(float2*)(Y + (size_t)(r0+8)*COUTT + cb) = make_float2(v2, v3);
                }
            }
        }

        #pragma unroll
        for (int off = 4; off <= 16; off <<= 1) {
            #pragma unroll
            for (int nf = 0; nf < 8; nf++)
                #pragma unroll
                for (int e = 0; e < 2; e++) {
                    s16[nf][e] += __shfl_xor_sync(0xffffffffu, s16[nf][e], off);
                    q16[nf][e] += __shfl_xor_sync(0xffffffffu, q16[nf][e], off);
                    m16[nf][e] = fmaxf(m16[nf][e], __shfl_xor_sync(0xffffffffu, m16[nf][e], off));
                }
        }
        if (gg == 0) {
            #pragma unroll
            for (int nf = 0; nf < 8; nf++)
                #pragma unroll
                for (int e = 0; e < 2; e++) {
                    int cl = wn*64 + nf*8 + 2*tq + e;
                    red_s[wm][cl] = s16[nf][e];
                    red_q[wm][cl] = q16[nf][e];
                    if (MODE == 2) red_m[wm][cl] = m16[nf][e];
                }
        }
        __syncthreads();

        if (tid < 128) {
            int c = tid;
            float ss = red_s[0][c] + red_s[1][c] + red_s[2][c] + red_s[3][c];
            float qq = red_q[0][c] + red_q[1][c] + red_q[2][c] + red_q[3][c];
            size_t pb = (size_t)t * (2*COUTT);
            g_part[pb + colTile + c]         = ss;
            g_part[pb + COUTT + colTile + c] = qq;
            if (MODE == 2) {
                #pragma unroll
                for (int wmi = 0; wmi < 4; wmi++)
                    g_gmax[((size_t)(t*4 + wmi))*COUT3 + colTile + c] = red_m[wmi][c];
            }
        }
    }
}

// ---------------------------------------------------------------------------
// BN finalize (fixed-order, deterministic)
// ---------------------------------------------------------------------------
__global__ void bn_finalize_kernel(int C,
                                   const float* __restrict__ g,
                                   const float* __restrict__ beta,
                                   float* __restrict__ bn_a,
                                   float* __restrict__ bn_c) {
    __shared__ float sh_s[256], sh_q[256];
    int ch = blockIdx.x;
    int t  = threadIdx.x;
    float s = 0.f, q = 0.f;
    for (int b = t; b < NBLK; b += 256) {
        size_t base = (size_t)b * (2*C);
        s += g_part[base + ch];
        q += g_part[base + C + ch];
    }
    sh_s[t] = s; sh_q[t] = q;
    __syncthreads();
    for (int off = 128; off > 0; off >>= 1) {
        if (t < off) { sh_s[t] += sh_s[t+off]; sh_q[t] += sh_q[t+off]; }
        __syncthreads();
    }
    if (t == 0) {
        const float invR = 1.0f / (float)RROWS;
        float mu  = sh_s[0] * invR;
        float var = sh_q[0] * invR - mu*mu;
        float a = g[ch] * rsqrtf(var + 1e-5f);
        bn_a[ch] = a;
        bn_c[ch] = beta[ch] - a*mu;
    }
}

// ---------------------------------------------------------------------------
// Final: relu(a3*gmax + c3) -> out (a3>0 so BN+relu commute with max)
// ---------------------------------------------------------------------------
__global__ void final_out_kernel(const float* __restrict__ bn_a,
                                 const float* __restrict__ bn_c,
                                 float* __restrict__ out) {
    int grp = blockIdx.x;
    int co  = threadIdx.x;
    float v = g_gmax[(size_t)grp*COUT3 + co];
    float r = fmaxf(fmaf(bn_a[co], v, bn_c[co]), 0.f);
    int b = grp >> 10, m = grp & 1023;
    out[OUT_XYZ_ELEMS + ((size_t)(b*COUT3 + co))*MM + m] = r;
}

// ---------------------------------------------------------------------------
// host launcher.  NOTE launch order: gemm_lm<0> is launch index 3 so the
// fixed ncu window (-s) lands on it next profile.
// ---------------------------------------------------------------------------
extern "C" void kernel_launch(void* const* d_in, const int* in_sizes, int n_in,
                              void* d_out, int out_size) {
    const float* xyz     = (const float*)d_in[0];
    const float* feat    = (const float*)d_in[1];
    const int*   indices = (const int*)  d_in[2];
    const float* w1 = (const float*)d_in[3];
    const float* b1 = (const float*)d_in[4];
    const float* g1 = (const float*)d_in[5];
    const float* e1 = (const float*)d_in[6];
    const float* w2 = (const float*)d_in[7];
    const float* b2 = (const float*)d_in[8];
    const float* g2 = (const float*)d_in[9];
    const float* e2 = (const float*)d_in[10];
    const float* w3 = (const float*)d_in[11];
    const float* b3 = (const float*)d_in[12];
    const float* g3 = (const float*)d_in[13];
    const float* e3 = (const float*)d_in[14];
    float* out = (float*)d_out;

    float *Y1, *Y2, *bn;
    unsigned char *w1s, *w2s, *w3s;
    cudaGetSymbolAddress((void**)&Y1,  g_Y1);
    cudaGetSymbolAddress((void**)&Y2,  g_Y2);
    cudaGetSymbolAddress((void**)&bn,  g_bn);
    cudaGetSymbolAddress((void**)&w1s, g_w1s);
    cudaGetSymbolAddress((void**)&w2s, g_w2s);
    cudaGetSymbolAddress((void**)&w3s, g_w3s);
    float* a1 = bn;            float* c1 = bn + COUT3;
    float* a2 = bn + 2*COUT3;  float* c2 = bn + 3*COUT3;
    float* a3 = bn + 4*COUT3;  float* c3 = bn + 5*COUT3;

    int smem1  = 2*18*SEGB + 128*128*4;   // 212992
    int smem23 = 2*16*SEGB + 128*128*4;   // 196608
    cudaFuncSetAttribute(gemm_lm<0>, cudaFuncAttributeMaxDynamicSharedMemorySize, smem1);
    cudaFuncSetAttribute(gemm_lm<1>, cudaFuncAttributeMaxDynamicSharedMemorySize, smem23);
    cudaFuncSetAttribute(gemm_lm<2>, cudaFuncAttributeMaxDynamicSharedMemorySize, smem23);

    // index 0..2: prep needed by gemm0
    splitw_kernel<<<COUT1, 144>>>(w1, w1s, 131, 18, 1);                     // 0
    {
        dim3 blk(32, 8);
        dim3 grd(NN/128, CC/32, BB);
        transpose_feat_kernel<<<grd, blk>>>(feat);                          // 1
    }
    ballquery_kernel<<<(BB*MM*32)/256, 256>>>(xyz, indices, out);           // 2

    // index 3: layer 1 GEMM (profiling target)
    gemm_lm<0><<<dim3(148,1), 256, smem1>>>(nullptr, w1s, b1, nullptr, nullptr,
                                            Y1, xyz, out);                  // 3
    bn_finalize_kernel<<<COUT1, 256>>>(COUT1, g1, e1, a1, c1);              // 4

    splitw_kernel<<<COUT2, 128>>>(w2, w2s, 128, 16, 0);                     // 5
    gemm_lm<1><<<dim3(148,1), 256, smem23>>>(Y1, w2s, b2, a1, c1,
                                             Y2, nullptr, nullptr);         // 6
    bn_finalize_kernel<<<COUT2, 256>>>(COUT2, g2, e2, a2, c2);              // 7

    splitw_kernel<<<COUT3, 128>>>(w3, w3s, 128, 16, 0);                     // 8
    gemm_lm<2><<<dim3(74,2), 256, smem23>>>(Y2, w3s, b3, a2, c2,
                                            nullptr, nullptr, nullptr);     // 9
    bn_finalize_kernel<<<COUT3, 256>>>(COUT3, g3, e3, a3, c3);              // 10

    final_out_kernel<<<NGRP, COUT3>>>(a3, c3, out);                         // 11
}

// round 10
// speedup vs baseline: 2.3813x; 1.1446x over previous
#include <cuda_runtime.h>
#include <cuda_bf16.h>
#include <math.h>
#include <stdint.h>

// ---------------------------------------------------------------------------
// Problem constants
// ---------------------------------------------------------------------------
#define BB 4
#define NN 16384
#define CC 128
#define MM 1024
#define KK 32
#define RROWS (BB*MM*KK)        // 131072
#define COUT1 128
#define COUT2 128
#define COUT3 256
#define NBLK (RROWS/128)        // 1024 row-tiles
#define NGRP (BB*MM)            // 4096
#define OUT_XYZ_ELEMS (BB*MM*3) // 12288
#define SEGB 4096               // one W segment: 128 rows x 32B

// ---------------------------------------------------------------------------
// Scratch (static device globals)
// ---------------------------------------------------------------------------
__device__ float g_featT[(size_t)BB*NN*CC];          // 32 MB (B,N,C)
__device__ int   g_idx[(size_t)BB*MM*KK];            // 512 KB
__device__ float g_Y1[(size_t)RROWS*COUT1];          // 64 MB
__device__ float g_Y2[(size_t)RROWS*COUT2];          // 64 MB
__device__ float g_gmax[(size_t)NGRP*COUT3];         // 4 MB
__device__ unsigned char g_w1s[18*SEGB];             // 9 chunks x {hi,lo} segs
__device__ unsigned char g_w2s[16*SEGB];
__device__ unsigned char g_w3s[2*16*SEGB];           // 2 col-tiles
__device__ float g_part[(size_t)4*NBLK*2*COUT3];     // per (tile,warp-row) partials
__device__ float g_bn[6*COUT3];

// ---------------------------------------------------------------------------
// helpers
// ---------------------------------------------------------------------------
__device__ __forceinline__ uint32_t smem_u32(const void* p) {
    uint32_t a;
    asm("{ .reg .u64 t; cvta.to.shared.u64 t, %1; cvt.u32.u64 %0, t; }"
        : "=r"(a) : "l"(p));
    return a;
}
__device__ __forceinline__ void ldm_x4(uint32_t* r, uint32_t addr) {
    asm volatile("ldmatrix.sync.aligned.m8n8.x4.shared.b16 {%0,%1,%2,%3}, [%4];"
        : "=r"(r[0]), "=r"(r[1]), "=r"(r[2]), "=r"(r[3]) : "r"(addr));
}
__device__ __forceinline__ void mma16816(float* c,
        const uint32_t* a, uint32_t b0, uint32_t b1) {
    asm volatile(
        "mma.sync.aligned.m16n8k16.row.col.f32.bf16.bf16.f32 "
        "{%0,%1,%2,%3}, {%4,%5,%6,%7}, {%8,%9}, {%0,%1,%2,%3};\n"
        : "+f"(c[0]), "+f"(c[1]), "+f"(c[2]), "+f"(c[3])
        : "r"(a[0]), "r"(a[1]), "r"(a[2]), "r"(a[3]), "r"(b0), "r"(b1));
}
// round-to-nearest bf16 hi/lo split of a float2, packed as bf16x2 words
__device__ __forceinline__ void split2(float2 v, uint32_t& hi, uint32_t& lo) {
    uint32_t t0 = __float_as_uint(v.x) + 0x8000u;
    uint32_t t1 = __float_as_uint(v.y) + 0x8000u;
    float h0 = __uint_as_float(t0 & 0xFFFF0000u);
    float h1 = __uint_as_float(t1 & 0xFFFF0000u);
    hi = __byte_perm(t0, t1, 0x7632);
    uint32_t l0 = __float_as_uint(v.x - h0) + 0x8000u;
    uint32_t l1 = __float_as_uint(v.y - h1) + 0x8000u;
    lo = __byte_perm(l0, l1, 0x7632);
}
#define CP_ASYNC16(dst, src) \
    asm volatile("cp.async.cg.shared.global [%0], [%1], 16;" :: "r"(dst), "l"(src))
#define CP_COMMIT() asm volatile("cp.async.commit_group;" ::: "memory")
#define CP_WAIT0()  asm volatile("cp.async.wait_group 0;" ::: "memory")

// ---------------------------------------------------------------------------
// 1) transpose features (B,C,N) -> (B,N,C).  256 thr, float4 both directions.
// ---------------------------------------------------------------------------
__global__ void transpose_feat_kernel(const float* __restrict__ f) {
    __shared__ __align__(16) float tile[32][132];
    int b  = blockIdx.z;
    int n0 = blockIdx.x * 128;
    int c0 = blockIdx.y * 32;
    int tx = threadIdx.x, ty = threadIdx.y;   // (32, 8)
    #pragma unroll
    for (int i = 0; i < 4; i++) {
        int c = ty*4 + i;
        float4 v = *(const float4*)(f + ((size_t)b*CC + c0 + c)*NN + n0 + tx*4);
        *(float4*)&tile[c][tx*4] = v;
    }
    __syncthreads();
    int t = ty*32 + tx;
    int n = t & 127, cg = t >> 7;
    #pragma unroll
    for (int i = 0; i < 4; i++) {
        int c = cg*16 + i*4;
        float4 v = make_float4(tile[c][n], tile[c+1][n], tile[c+2][n], tile[c+3][n]);
        *(float4*)(g_featT + ((size_t)b*NN + n0 + n)*CC + c0 + c) = v;
    }
}

// ---------------------------------------------------------------------------
// 2) ball query: warp per query, 64 points/iteration (2 per lane).
// ---------------------------------------------------------------------------
__global__ void ballquery_kernel(const float* __restrict__ xyz,
                                 const int*   __restrict__ indices,
                                 float*       __restrict__ out_newxyz) {
    int gw   = (blockIdx.x * blockDim.x + threadIdx.x) >> 5;
    int lane = threadIdx.x & 31;
    if (gw >= BB*MM) return;
    int b = gw >> 10;
    const float R2 = (float)(0.4 * 0.4);
    const float* base = xyz + (size_t)b*NN*3;
    int ctr = indices[gw];
    float cx = base[ctr*3+0], cy = base[ctr*3+1], cz = base[ctr*3+2];
    if (lane < 3) out_newxyz[gw*3 + lane] = base[ctr*3+lane];

    unsigned lt = (1u << lane) - 1u;
    int cnt = 0, first = 0;
    int* myidx = g_idx + (size_t)gw*KK;
    for (int j0 = 0; j0 < NN; j0 += 64) {
        int ja = j0 + lane, jb = j0 + 32 + lane;
        float dxa = base[ja*3+0]-cx, dya = base[ja*3+1]-cy, dza = base[ja*3+2]-cz;
        float dxb = base[jb*3+0]-cx, dyb = base[jb*3+1]-cy, dzb = base[jb*3+2]-cz;
        bool wa = (dxa*dxa + dya*dya + dza*dza) < R2;
        bool wb = (dxb*dxb + dyb*dyb + dzb*dzb) < R2;
        unsigned m1 = __ballot_sync(0xffffffffu, wa);
        unsigned m2 = __ballot_sync(0xffffffffu, wb);
        if (m1 | m2) {
            if (cnt == 0)
                first = m1 ? (j0 + __ffs(m1) - 1) : (j0 + 32 + __ffs(m2) - 1);
            int c1 = __popc(m1);
            int p1 = __popc(m1 & lt);
            if (wa && (cnt + p1) < KK) myidx[cnt + p1] = ja;
            int p2 = __popc(m2 & lt);
            if (wb && (cnt + c1 + p2) < KK) myidx[cnt + c1 + p2] = jb;
            cnt += c1 + __popc(m2);
            if (cnt >= KK) break;
        }
    }
    int ce = cnt < KK ? cnt : KK;
    if (lane >= ce) myidx[lane] = first;
}

// ---------------------------------------------------------------------------
// 3) weight split into per-segment smem image:
//    layout per col-tile: [chunk c][seg 0=hi,1=lo][n(128)][16 bf16]
//    perm=1 (layer1): k<128 -> w[:,3+k]; 128..130 -> w[:,k-128]; else 0
// ---------------------------------------------------------------------------
__global__ void splitw_kernel(const float* __restrict__ w,
                              unsigned char* __restrict__ out,
                              int Cin, int nSeg, int perm) {
    int o = blockIdx.x, k = threadIdx.x;
    int wt = o >> 7, n = o & 127;
    float v;
    if (perm) {
        if (k < 128)      v = w[o*Cin + 3 + k];
        else if (k < 131) v = w[o*Cin + (k - 128)];
        else              v = 0.f;
    } else {
        v = (k < Cin) ? w[o*Cin + k] : 0.f;
    }
    __nv_bfloat16 h = __float2bfloat16_rn(v);
    __nv_bfloat16 l = __float2bfloat16_rn(v - __bfloat162float(h));
    int c = k >> 4, kk = k & 15;
    unsigned char* base = out + (size_t)wt * nSeg * SEGB;
    *(__nv_bfloat16*)(base + ((size_t)(2*c+0)*128 + n)*32 + kk*2) = h;
    *(__nv_bfloat16*)(base + ((size_t)(2*c+1)*128 + n)*32 + kk*2) = l;
}

// ---------------------------------------------------------------------------
// Persistent register-direct fused GEMM.  Y = act(A) @ W^T + bias (+stats/max)
//   MODE 0: A = virtual gathered X1 (featT + dxyz), K=144 (9 chunks) -> Y1
//   MODE 1: A = Y1, act=relu(bn).  K=128.                            -> Y2
//   MODE 2: A = Y2, act=relu(bn).  stats + K-group max, no Y.
// Block 128x128, 8 warps (wm 0..3 x wn 0..1), warp tile 32x64.
// A fragments are built DIRECTLY in registers from global loads (BN/ReLU +
// hi/lo split in regs) -- no smem for A, ZERO barriers in the tile loop.
// W resident in smem (ldmatrix), loaded once. Per-warp stats partials.
// ---------------------------------------------------------------------------
template<int MODE>
__global__ __launch_bounds__(256, 1)
void gemm_rr(const float* __restrict__ A,
             const unsigned char* __restrict__ Wt,
             const float* __restrict__ bias,
             const float* __restrict__ bn_a, const float* __restrict__ bn_c,
             float* __restrict__ Y,
             const float* __restrict__ xyz, const float* __restrict__ newxyz) {
    constexpr int NCH   = (MODE == 0) ? 9 : 8;
    constexpr int NSEG  = 2 * NCH;
    constexpr int NLD   = 8;                 // fp32 chunks to load (dxyz separate)
    constexpr int COUTT = (MODE == 2) ? 256 : 128;

    extern __shared__ unsigned char dsm[];
    unsigned char* Wsm = dsm;                // NSEG*SEGB

    __shared__ float s_bias[128];
    __shared__ float s_bna[128], s_bnc[128];

    int tid  = threadIdx.x;
    int lane = tid & 31, warp = tid >> 5;
    int wm = warp >> 1, wn = warp & 1;
    int colTile = blockIdx.y * 128;
    int gg = lane >> 2, tq = lane & 3;

    uint32_t wsm_a = smem_u32(Wsm);

    if (tid < 128) {
        s_bias[tid] = bias[colTile + tid];
        if (MODE != 0) { s_bna[tid] = bn_a[tid]; s_bnc[tid] = bn_c[tid]; }
    }
    // W tile -> smem (once per CTA)
    {
        const unsigned char* wsrc = Wt + (size_t)blockIdx.y * NSEG * SEGB;
        for (int i = tid; i < NSEG*256; i += 256)
            CP_ASYNC16(wsm_a + i*16, wsrc + (size_t)i*16);
        CP_COMMIT();
    }
    CP_WAIT0();
    __syncthreads();          // the ONLY barrier

    uint32_t boff = (uint32_t)((wn*64 + (lane & 7) + ((lane >> 4) & 1)*8)*32
                               + ((lane >> 3) & 1)*16);

    for (int t = blockIdx.x; t < NBLK; t += gridDim.x) {
        // ---- per-tile row sources: (mf, h) -> row = t*128+wm*32+mf*16+h*8+gg
        const float* srcp[2][2];
        float dxr[2][2], dyr[2][2], dzr[2][2];
        #pragma unroll
        for (int mf = 0; mf < 2; mf++)
            #pragma unroll
            for (int h = 0; h < 2; h++) {
                int rg = t*128 + wm*32 + mf*16 + h*8 + gg;
                if (MODE == 0) {
                    int jj = g_idx[rg];
                    int bb = rg >> 15;
                    srcp[mf][h] = g_featT + ((size_t)bb*NN + jj)*CC;
                    const float* pp = xyz    + ((size_t)bb*NN + jj)*3;
                    const float* cq = newxyz + (size_t)(rg >> 5)*3;
                    dxr[mf][h] = pp[0]-cq[0];
                    dyr[mf][h] = pp[1]-cq[1];
                    dzr[mf][h] = pp[2]-cq[2];
                } else {
                    srcp[mf][h] = A + (size_t)rg*128;
                }
            }

        // ---- chunk loader: 8 float2 per chunk into buf
        // buf index: mf*4 + h*2 + {0 = k0 (cols 2tq,2tq+1), 1 = k8 (+8)}
        auto loadChunk = [&](int c, float2* buf) {
            #pragma unroll
            for (int mf = 0; mf < 2; mf++)
                #pragma unroll
                for (int h = 0; h < 2; h++) {
                    const float* p = srcp[mf][h] + c*16 + 2*tq;
                    buf[mf*4 + h*2 + 0] = *(const float2*)p;
                    buf[mf*4 + h*2 + 1] = *(const float2*)(p + 8);
                }
        };

        float acc[2][8][4];
        #pragma unroll
        for (int mf = 0; mf < 2; mf++)
            #pragma unroll
            for (int nf = 0; nf < 8; nf++)
                #pragma unroll
                for (int r2 = 0; r2 < 4; r2++) acc[mf][nf][r2] = 0.f;

        float2 bufA[8], bufB[8];
        loadChunk(0, bufA);

        #pragma unroll
        for (int c = 0; c < NCH; c++) {
            float2* cur = (c & 1) ? bufB : bufA;
            float2* nxt = (c & 1) ? bufA : bufB;
            if (c + 1 < NLD) loadChunk(c + 1, nxt);   // prefetch over this mma

            // ---- build A fragments in registers ----
            uint32_t ah[2][4], al[2][4];
            if (MODE == 0 && c == 8) {
                #pragma unroll
                for (int mf = 0; mf < 2; mf++) {
                    #pragma unroll
                    for (int h = 0; h < 2; h++) {
                        float2 v;   // cols 128+2tq, 129+2tq
                        v.x = (tq == 0) ? dxr[mf][h] : (tq == 1) ? dzr[mf][h] : 0.f;
                        v.y = (tq == 0) ? dyr[mf][h] : 0.f;
                        split2(v, ah[mf][h], al[mf][h]);      // regs 0 (h=0), 1 (h=1)
                    }
                    ah[mf][2] = 0u; al[mf][2] = 0u;            // k8 cols >= 136: zero
                    ah[mf][3] = 0u; al[mf][3] = 0u;
                }
            } else {
                float2 ba0, bc0, ba8, bc8;
                if (MODE != 0) {
                    ba0 = *(const float2*)&s_bna[c*16 + 2*tq];
                    bc0 = *(const float2*)&s_bnc[c*16 + 2*tq];
                    ba8 = *(const float2*)&s_bna[c*16 + 2*tq + 8];
                    bc8 = *(const float2*)&s_bnc[c*16 + 2*tq + 8];
                }
                #pragma unroll
                for (int mf = 0; mf < 2; mf++)
                    #pragma unroll
                    for (int h = 0; h < 2; h++) {
                        float2 v0 = cur[mf*4 + h*2 + 0];
                        float2 v8 = cur[mf*4 + h*2 + 1];
                        if (MODE != 0) {
                            v0.x = fmaxf(fmaf(v0.x, ba0.x, bc0.x), 0.f);
                            v0.y = fmaxf(fmaf(v0.y, ba0.y, bc0.y), 0.f);
                            v8.x = fmaxf(fmaf(v8.x, ba8.x, bc8.x), 0.f);
                            v8.y = fmaxf(fmaf(v8.y, ba8.y, bc8.y), 0.f);
                        }
                        split2(v0, ah[mf][h],     al[mf][h]);      // reg h   (k0)
                        split2(v8, ah[mf][2 + h], al[mf][2 + h]);  // reg 2+h (k8)
                    }
            }

            // ---- B fragments from smem ----
            uint32_t bh[8][2], bl[8][2];
            #pragma unroll
            for (int j = 0; j < 4; j++) {
                uint32_t r4[4];
                ldm_x4(r4, wsm_a + (uint32_t)(2*c)*SEGB + boff + j*512);
                bh[2*j][0] = r4[0]; bh[2*j][1] = r4[1];
                bh[2*j+1][0] = r4[2]; bh[2*j+1][1] = r4[3];
                ldm_x4(r4, wsm_a + (uint32_t)(2*c+1)*SEGB + boff + j*512);
                bl[2*j][0] = r4[0]; bl[2*j][1] = r4[1];
                bl[2*j+1][0] = r4[2]; bl[2*j+1][1] = r4[3];
            }
            #pragma unroll
            for (int nf = 0; nf < 8; nf++) {
                mma16816(acc[0][nf], ah[0], bh[nf][0], bh[nf][1]);
                mma16816(acc[1][nf], ah[1], bh[nf][0], bh[nf][1]);
                mma16816(acc[0][nf], ah[0], bl[nf][0], bl[nf][1]);
                mma16816(acc[1][nf], ah[1], bl[nf][0], bl[nf][1]);
                mma16816(acc[0][nf], al[0], bh[nf][0], bh[nf][1]);
                mma16816(acc[1][nf], al[1], bh[nf][0], bh[nf][1]);
            }
        }

        // ---- epilogue: bias, Y write, per-warp stats/max (no barriers) ----
        float bs[8][2];
        #pragma unroll
        for (int nf = 0; nf < 8; nf++) {
            int col = wn*64 + nf*8 + 2*tq;
            bs[nf][0] = s_bias[col];
            bs[nf][1] = s_bias[col+1];
        }
        float s16[8][2], q16[8][2], m16[8][2];
        #pragma unroll
        for (int nf = 0; nf < 8; nf++)
            #pragma unroll
            for (int e = 0; e < 2; e++) { s16[nf][e]=0.f; q16[nf][e]=0.f; m16[nf][e]=-3.4e38f; }

        #pragma unroll
        for (int mf = 0; mf < 2; mf++) {
            #pragma unroll
            for (int nf = 0; nf < 8; nf++) {
                float v0 = acc[mf][nf][0] + bs[nf][0];
                float v1 = acc[mf][nf][1] + bs[nf][1];
                float v2 = acc[mf][nf][2] + bs[nf][0];
                float v3 = acc[mf][nf][3] + bs[nf][1];
                s16[nf][0] += v0 + v2;  s16[nf][1] += v1 + v3;
                q16[nf][0] = fmaf(v0,v0,fmaf(v2,v2,q16[nf][0]));
                q16[nf][1] = fmaf(v1,v1,fmaf(v3,v3,q16[nf][1]));
                m16[nf][0] = fmaxf(m16[nf][0], fmaxf(v0, v2));
                m16[nf][1] = fmaxf(m16[nf][1], fmaxf(v1, v3));
                if (MODE != 2) {
                    int r0 = t*128 + wm*32 + mf*16 + gg;
                    int cb = colTile + wn*64 + nf*8 + 2*tq;
                    *(float2*)(Y + (size_t)r0*COUTT + cb)     = make_float2(v0, v1);
                    *(float2*)(Y + (size_t)(r0+8)*COUTT + cb) = make_float2(v2, v3);
                }
            }
        }

        #pragma unroll
        for (int off = 4; off <= 16; off <<= 1) {
            #pragma unroll
            for (int nf = 0; nf < 8; nf++)
                #pragma unroll
                for (int e = 0; e < 2; e++) {
                    s16[nf][e] += __shfl_xor_sync(0xffffffffu, s16[nf][e], off);
                    q16[nf][e] += __shfl_xor_sync(0xffffffffu, q16[nf][e], off);
                    m16[nf][e] = fmaxf(m16[nf][e], __shfl_xor_sync(0xffffffffu, m16[nf][e], off));
                }
        }
        if (gg == 0) {
            size_t pb = (size_t)(t*4 + wm) * (2*COUTT);
            #pragma unroll
            for (int nf = 0; nf < 8; nf++)
                #pragma unroll
                for (int e = 0; e < 2; e++) {
                    int cl = wn*64 + nf*8 + 2*tq + e;
                    g_part[pb + colTile + cl]         = s16[nf][e];
                    g_part[pb + COUTT + colTile + cl] = q16[nf][e];
                    if (MODE == 2)
                        g_gmax[((size_t)(t*4 + wm))*COUT3 + colTile + cl] = m16[nf][e];
                }
        }
    }
}

// ---------------------------------------------------------------------------
// BN finalize: fixed-order reduce over 4*NBLK per-warp partials
// ---------------------------------------------------------------------------
__global__ void bn_finalize_kernel(int C,
                                   const float* __restrict__ g,
                                   const float* __restrict__ beta,
                                   float* __restrict__ bn_a,
                                   float* __restrict__ bn_c) {
    __shared__ float sh_s[256], sh_q[256];
    int ch = blockIdx.x;
    int t  = threadIdx.x;
    float s = 0.f, q = 0.f;
    for (int b = t; b < 4*NBLK; b += 256) {
        size_t base = (size_t)b * (2*C);
        s += g_part[base + ch];
        q += g_part[base + C + ch];
    }
    sh_s[t] = s; sh_q[t] = q;
    __syncthreads();
    for (int off = 128; off > 0; off >>= 1) {
        if (t < off) { sh_s[t] += sh_s[t+off]; sh_q[t] += sh_q[t+off]; }
        __syncthreads();
    }
    if (t == 0) {
        const float invR = 1.0f / (float)RROWS;
        float mu  = sh_s[0] * invR;
        float var = sh_q[0] * invR - mu*mu;
        float a = g[ch] * rsqrtf(var + 1e-5f);
        bn_a[ch] = a;
        bn_c[ch] = beta[ch] - a*mu;
    }
}

// ---------------------------------------------------------------------------
// Final: relu(a3*gmax + c3) -> out (a3>0 so BN+relu commute with max)
// ---------------------------------------------------------------------------
__global__ void final_out_kernel(const float* __restrict__ bn_a,
                                 const float* __restrict__ bn_c,
                                 float* __restrict__ out) {
    int grp = blockIdx.x;
    int co  = threadIdx.x;
    float v = g_gmax[(size_t)grp*COUT3 + co];
    float r = fmaxf(fmaf(bn_a[co], v, bn_c[co]), 0.f);
    int b = grp >> 10, m = grp & 1023;
    out[OUT_XYZ_ELEMS + ((size_t)(b*COUT3 + co))*MM + m] = r;
}

// ---------------------------------------------------------------------------
// host launcher (gemm_rr<0> stays at launch index 3 for the ncu window)
// ---------------------------------------------------------------------------
extern "C" void kernel_launch(void* const* d_in, const int* in_sizes, int n_in,
                              void* d_out, int out_size) {
    const float* xyz     = (const float*)d_in[0];
    const float* feat    = (const float*)d_in[1];
    const int*   indices = (const int*)  d_in[2];
    const float* w1 = (const float*)d_in[3];
    const float* b1 = (const float*)d_in[4];
    const float* g1 = (const float*)d_in[5];
    const float* e1 = (const float*)d_in[6];
    const float* w2 = (const float*)d_in[7];
    const float* b2 = (const float*)d_in[8];
    const float* g2 = (const float*)d_in[9];
    const float* e2 = (const float*)d_in[10];
    const float* w3 = (const float*)d_in[11];
    const float* b3 = (const float*)d_in[12];
    const float* g3 = (const float*)d_in[13];
    const float* e3 = (const float*)d_in[14];
    float* out = (float*)d_out;

    float *Y1, *Y2, *bn;
    unsigned char *w1s, *w2s, *w3s;
    cudaGetSymbolAddress((void**)&Y1,  g_Y1);
    cudaGetSymbolAddress((void**)&Y2,  g_Y2);
    cudaGetSymbolAddress((void**)&bn,  g_bn);
    cudaGetSymbolAddress((void**)&w1s, g_w1s);
    cudaGetSymbolAddress((void**)&w2s, g_w2s);
    cudaGetSymbolAddress((void**)&w3s, g_w3s);
    float* a1 = bn;            float* c1 = bn + COUT3;
    float* a2 = bn + 2*COUT3;  float* c2 = bn + 3*COUT3;
    float* a3 = bn + 4*COUT3;  float* c3 = bn + 5*COUT3;

    int smem1  = 18*SEGB;     // 72 KB
    int smem23 = 16*SEGB;     // 64 KB
    cudaFuncSetAttribute(gemm_rr<0>, cudaFuncAttributeMaxDynamicSharedMemorySize, smem1);
    cudaFuncSetAttribute(gemm_rr<1>, cudaFuncAttributeMaxDynamicSharedMemorySize, smem23);
    cudaFuncSetAttribute(gemm_rr<2>, cudaFuncAttributeMaxDynamicSharedMemorySize, smem23);

    // index 0..2: prep needed by gemm0
    splitw_kernel<<<COUT1, 144>>>(w1, w1s, 131, 18, 1);                     // 0
    {
        dim3 blk(32, 8);
        dim3 grd(NN/128, CC/32, BB);
        transpose_feat_kernel<<<grd, blk>>>(feat);                          // 1
    }
    ballquery_kernel<<<(BB*MM*32)/256, 256>>>(xyz, indices, out);           // 2

    // index 3: layer 1 GEMM (profiling target)
    gemm_rr<0><<<dim3(148,1), 256, smem1>>>(nullptr, w1s, b1, nullptr, nullptr,
                                            Y1, xyz, out);                  // 3
    bn_finalize_kernel<<<COUT1, 256>>>(COUT1, g1, e1, a1, c1);              // 4

    splitw_kernel<<<COUT2, 128>>>(w2, w2s, 128, 16, 0);                     // 5
    gemm_rr<1><<<dim3(148,1), 256, smem23>>>(Y1, w2s, b2, a1, c1,
                                             Y2, nullptr, nullptr);         // 6
    bn_finalize_kernel<<<COUT2, 256>>>(COUT2, g2, e2, a2, c2);              // 7

    splitw_kernel<<<COUT3, 128>>>(w3, w3s, 128, 16, 0);                     // 8
    gemm_rr<2><<<dim3(74,2), 256, smem23>>>(Y2, w3s, b3, a2, c2,
                                            nullptr, nullptr, nullptr);     // 9
    bn_finalize_kernel<<<COUT3, 256>>>(COUT3, g3, e3, a3, c3);              // 10

    final_out_kernel<<<NGRP, COUT3>>>(a3, c3, out);                         // 11
}

// round 14
// speedup vs baseline: 2.5823x; 1.0844x over previous
#include <cuda_runtime.h>
#include <cuda_bf16.h>
#include <math.h>
#include <stdint.h>

// ---------------------------------------------------------------------------
// Problem constants
// ---------------------------------------------------------------------------
#define BB 4
#define NN 16384
#define CC 128
#define MM 1024
#define KK 32
#define RROWS (BB*MM*KK)        // 131072
#define COUT1 128
#define COUT2 128
#define COUT3 256
#define NBLK (RROWS/128)        // 1024 row-tiles
#define NGRP (BB*MM)            // 4096
#define OUT_XYZ_ELEMS (BB*MM*3) // 12288
#define SEGB 4096               // one W segment: 128 rows x 32B
#define SROW 136                // A-stage row stride in floats (136 % 32 == 8)
#define STAGEF (4*32*SROW)      // one stage buffer in floats (4 groups x 32 rows)

// ---------------------------------------------------------------------------
// Scratch (static device globals)
// ---------------------------------------------------------------------------
__device__ float g_featT[(size_t)BB*NN*CC];          // 32 MB (B,N,C)
__device__ int   g_idx[(size_t)BB*MM*KK];            // 512 KB
__device__ float g_Y1[(size_t)RROWS*COUT1];          // 64 MB
__device__ float g_Y2[(size_t)RROWS*COUT2];          // 64 MB
__device__ float g_gmax[(size_t)NGRP*COUT3];         // 4 MB
__device__ unsigned char g_w1s[18*SEGB];             // 9 chunks x {hi,lo} segs
__device__ unsigned char g_w2s[16*SEGB];
__device__ unsigned char g_w3s[2*16*SEGB];           // 2 col-tiles
__device__ float g_part[(size_t)4*NBLK*2*COUT3];     // per (tile,warp-row) partials
__device__ float g_bn[6*COUT3];

// ---------------------------------------------------------------------------
// helpers
// ---------------------------------------------------------------------------
__device__ __forceinline__ uint32_t smem_u32(const void* p) {
    uint32_t a;
    asm("{ .reg .u64 t; cvta.to.shared.u64 t, %1; cvt.u32.u64 %0, t; }"
        : "=r"(a) : "l"(p));
    return a;
}
__device__ __forceinline__ void ldm_x4(uint32_t* r, uint32_t addr) {
    asm volatile("ldmatrix.sync.aligned.m8n8.x4.shared.b16 {%0,%1,%2,%3}, [%4];"
        : "=r"(r[0]), "=r"(r[1]), "=r"(r[2]), "=r"(r[3]) : "r"(addr));
}
__device__ __forceinline__ void mma16816(float* c,
        const uint32_t* a, uint32_t b0, uint32_t b1) {
    asm volatile(
        "mma.sync.aligned.m16n8k16.row.col.f32.bf16.bf16.f32 "
        "{%0,%1,%2,%3}, {%4,%5,%6,%7}, {%8,%9}, {%0,%1,%2,%3};\n"
        : "+f"(c[0]), "+f"(c[1]), "+f"(c[2]), "+f"(c[3])
        : "r"(a[0]), "r"(a[1]), "r"(a[2]), "r"(a[3]), "r"(b0), "r"(b1));
}
// round-to-nearest bf16 hi/lo split of a float2, packed as bf16x2 words
__device__ __forceinline__ void split2(float2 v, uint32_t& hi, uint32_t& lo) {
    uint32_t t0 = __float_as_uint(v.x) + 0x8000u;
    uint32_t t1 = __float_as_uint(v.y) + 0x8000u;
    float h0 = __uint_as_float(t0 & 0xFFFF0000u);
    float h1 = __uint_as_float(t1 & 0xFFFF0000u);
    hi = __byte_perm(t0, t1, 0x7632);
    uint32_t l0 = __float_as_uint(v.x - h0) + 0x8000u;
    uint32_t l1 = __float_as_uint(v.y - h1) + 0x8000u;
    lo = __byte_perm(l0, l1, 0x7632);
}
#define CP_ASYNC16(dst, src) \
    asm volatile("cp.async.cg.shared.global [%0], [%1], 16;" :: "r"(dst), "l"(src))
#define CP_COMMIT() asm volatile("cp.async.commit_group;" ::: "memory")
#define CP_WAIT0()  asm volatile("cp.async.wait_group 0;" ::: "memory")
#define BAR_PAIR(id) asm volatile("bar.sync %0, 64;" :: "r"(id) : "memory")

// ---------------------------------------------------------------------------
// 1) transpose features (B,C,N) -> (B,N,C).  256 thr, float4 both directions.
// ---------------------------------------------------------------------------
__global__ void transpose_feat_kernel(const float* __restrict__ f) {
    __shared__ __align__(16) float tile[32][132];
    int b  = blockIdx.z;
    int n0 = blockIdx.x * 128;
    int c0 = blockIdx.y * 32;
    int tx = threadIdx.x, ty = threadIdx.y;   // (32, 8)
    #pragma unroll
    for (int i = 0; i < 4; i++) {
        int c = ty*4 + i;
        float4 v = *(const float4*)(f + ((size_t)b*CC + c0 + c)*NN + n0 + tx*4);
        *(float4*)&tile[c][tx*4] = v;
    }
    __syncthreads();
    int t = ty*32 + tx;
    int n = t & 127, cg = t >> 7;
    #pragma unroll
    for (int i = 0; i < 4; i++) {
        int c = cg*16 + i*4;
        float4 v = make_float4(tile[c][n], tile[c+1][n], tile[c+2][n], tile[c+3][n]);
        *(float4*)(g_featT + ((size_t)b*NN + n0 + n)*CC + c0 + c) = v;
    }
}

// ---------------------------------------------------------------------------
// 2) ball query: warp per query, 64 points/iteration (2 per lane).
// ---------------------------------------------------------------------------
__global__ void ballquery_kernel(const float* __restrict__ xyz,
                                 const int*   __restrict__ indices,
                                 float*       __restrict__ out_newxyz) {
    int gw   = (blockIdx.x * blockDim.x + threadIdx.x) >> 5;
    int lane = threadIdx.x & 31;
    if (gw >= BB*MM) return;
    int b = gw >> 10;
    const float R2 = (float)(0.4 * 0.4);
    const float* base = xyz + (size_t)b*NN*3;
    int ctr = indices[gw];
    float cx = base[ctr*3+0], cy = base[ctr*3+1], cz = base[ctr*3+2];
    if (lane < 3) out_newxyz[gw*3 + lane] = base[ctr*3+lane];

    unsigned lt = (1u << lane) - 1u;
    int cnt = 0, first = 0;
    int* myidx = g_idx + (size_t)gw*KK;
    for (int j0 = 0; j0 < NN; j0 += 64) {
        int ja = j0 + lane, jb = j0 + 32 + lane;
        float dxa = base[ja*3+0]-cx, dya = base[ja*3+1]-cy, dza = base[ja*3+2]-cz;
        float dxb = base[jb*3+0]-cx, dyb = base[jb*3+1]-cy, dzb = base[jb*3+2]-cz;
        bool wa = (dxa*dxa + dya*dya + dza*dza) < R2;
        bool wb = (dxb*dxb + dyb*dyb + dzb*dzb) < R2;
        unsigned m1 = __ballot_sync(0xffffffffu, wa);
        unsigned m2 = __ballot_sync(0xffffffffu, wb);
        if (m1 | m2) {
            if (cnt == 0)
                first = m1 ? (j0 + __ffs(m1) - 1) : (j0 + 32 + __ffs(m2) - 1);
            int c1 = __popc(m1);
            int p1 = __popc(m1 & lt);
            if (wa && (cnt + p1) < KK) myidx[cnt + p1] = ja;
            int p2 = __popc(m2 & lt);
            if (wb && (cnt + c1 + p2) < KK) myidx[cnt + c1 + p2] = jb;
            cnt += c1 + __popc(m2);
            if (cnt >= KK) break;
        }
    }
    int ce = cnt < KK ? cnt : KK;
    if (lane >= ce) myidx[lane] = first;
}

// ---------------------------------------------------------------------------
// 3) weight split into per-segment smem image:
//    layout per col-tile: [chunk c][seg 0=hi,1=lo][n(128)][16 bf16]
//    perm=1 (layer1): k<128 -> w[:,3+k]; 128..130 -> w[:,k-128]; else 0
// ---------------------------------------------------------------------------
__global__ void splitw_kernel(const float* __restrict__ w,
                              unsigned char* __restrict__ out,
                              int Cin, int nSeg, int perm) {
    int o = blockIdx.x, k = threadIdx.x;
    int wt = o >> 7, n = o & 127;
    float v;
    if (perm) {
        if (k < 128)      v = w[o*Cin + 3 + k];
        else if (k < 131) v = w[o*Cin + (k - 128)];
        else              v = 0.f;
    } else {
        v = (k < Cin) ? w[o*Cin + k] : 0.f;
    }
    __nv_bfloat16 h = __float2bfloat16_rn(v);
    __nv_bfloat16 l = __float2bfloat16_rn(v - __bfloat162float(h));
    int c = k >> 4, kk = k & 15;
    unsigned char* base = out + (size_t)wt * nSeg * SEGB;
    *(__nv_bfloat16*)(base + ((size_t)(2*c+0)*128 + n)*32 + kk*2) = h;
    *(__nv_bfloat16*)(base + ((size_t)(2*c+1)*128 + n)*32 + kk*2) = l;
}

// ---------------------------------------------------------------------------
// Persistent fused GEMM, smem-staged A.  Y = act(A) @ W^T + bias (+stats/max)
//   MODE 0: A = virtual gathered X1 (featT + dxyz), K=144 (9 chunks) -> Y1
//   MODE 1: A = Y1, act=relu(bn).  K=128.                            -> Y2
//   MODE 2: A = Y2, act=relu(bn).  stats + K-group max, no Y.
// Block 128x128, 8 warps (wm 0..3 x wn 0..1), warp tile 32x64.
// A rows are cp.async-staged whole-K into smem (coalesced, double-buffered),
// fragments read back as LDS.64 (stride 136 -> 2-phase conflict floor), then
// BN/ReLU + hi/lo split in registers.  NO __syncthreads in the tile loop --
// each wn-pair syncs via a 64-thread named barrier (bar.sync wm+1).
// Split precision: A,W {hi,lo}; products hi*hi + hi*lo + lo*hi.
// ---------------------------------------------------------------------------
template<int MODE>
__global__ __launch_bounds__(256, 1)
void gemm_rr(const float* __restrict__ A,
             const unsigned char* __restrict__ Wt,
             const float* __restrict__ bias,
             const float* __restrict__ bn_a, const float* __restrict__ bn_c,
             float* __restrict__ Y,
             const float* __restrict__ xyz, const float* __restrict__ newxyz) {
    constexpr int NCH   = (MODE == 0) ? 9 : 8;
    constexpr int NSEG  = 2 * NCH;
    constexpr int COUTT = (MODE == 2) ? 256 : 128;

    extern __shared__ unsigned char dsm[];
    unsigned char* Wsm = dsm;                        // NSEG*SEGB
    float* smA = (float*)(dsm + NSEG*SEGB);          // 2 * STAGEF floats

    __shared__ float s_bias[128];
    __shared__ float s_bna[128], s_bnc[128];

    int tid  = threadIdx.x;
    int lane = tid & 31, warp = tid >> 5;
    int wm = warp >> 1, wn = warp & 1;
    int colTile = blockIdx.y * 128;
    int gg = lane >> 2, tq = lane & 3;

    uint32_t wsm_a = smem_u32(Wsm);

    if (tid < 128) {
        s_bias[tid] = bias[colTile + tid];
        if (MODE != 0) { s_bna[tid] = bn_a[tid]; s_bnc[tid] = bn_c[tid]; }
    }
    // W tile -> smem (once per CTA)
    {
        const unsigned char* wsrc = Wt + (size_t)blockIdx.y * NSEG * SEGB;
        for (int i = tid; i < NSEG*256; i += 256)
            CP_ASYNC16(wsm_a + i*16, wsrc + (size_t)i*16);
        CP_COMMIT();
    }

    // ---- A stage prefetch: this warp stages 16 of its pair's 32 rows,
    //      whole K (128 floats), one coalesced cp.async row per instruction
    uint32_t smA_a = smem_u32(smA);
    auto prefetch = [&](int t, int buf) {
        if (t < NBLK) {
            #pragma unroll
            for (int i = 0; i < 16; i++) {
                int r  = wn*16 + i;                  // row within group
                int rg = t*128 + wm*32 + r;
                const float* src;
                if (MODE == 0) {
                    int jj = g_idx[rg];
                    int bb = rg >> 15;
                    src = g_featT + ((size_t)bb*NN + jj)*CC;
                } else {
                    src = A + (size_t)rg*128;
                }
                uint32_t dst = smA_a +
                    (uint32_t)(((buf*4 + wm)*32 + r)*SROW + lane*4)*4;
                CP_ASYNC16(dst, src + lane*4);
            }
        }
        CP_COMMIT();
    };

    prefetch(blockIdx.x, 0);
    CP_WAIT0();
    __syncthreads();          // once: W + first stage visible to everyone

    uint32_t boff = (uint32_t)((wn*64 + (lane & 7) + ((lane >> 4) & 1)*8)*32
                               + ((lane >> 3) & 1)*16);
    int buf = 0;

    for (int t = blockIdx.x; t < NBLK; t += gridDim.x) {
        // prefetch next tile into the other buffer (overlaps this compute)
        prefetch(t + gridDim.x, buf ^ 1);

        // ---- per-tile dxyz (MODE 0 only, fragment-resident)
        float dxr[2][2], dyr[2][2], dzr[2][2];
        if (MODE == 0) {
            #pragma unroll
            for (int mf = 0; mf < 2; mf++)
                #pragma unroll
                for (int h = 0; h < 2; h++) {
                    int rg = t*128 + wm*32 + mf*16 + h*8 + gg;
                    int jj = g_idx[rg];
                    int bb = rg >> 15;
                    const float* pp = xyz    + ((size_t)bb*NN + jj)*3;
                    const float* cq = newxyz + (size_t)(rg >> 5)*3;
                    dxr[mf][h] = pp[0]-cq[0];
                    dyr[mf][h] = pp[1]-cq[1];
                    dzr[mf][h] = pp[2]-cq[2];
                }
        }

        // fragment-row base offsets in the stage (floats)
        const float* arow[2][2];
        #pragma unroll
        for (int mf = 0; mf < 2; mf++)
            #pragma unroll
            for (int h = 0; h < 2; h++)
                arow[mf][h] = smA + (size_t)(((buf*4 + wm)*32
                                    + mf*16 + h*8 + gg)*SROW + 2*tq);

        float acc[2][8][4];
        #pragma unroll
        for (int mf = 0; mf < 2; mf++)
            #pragma unroll
            for (int nf = 0; nf < 8; nf++)
                #pragma unroll
                for (int r2 = 0; r2 < 4; r2++) acc[mf][nf][r2] = 0.f;

        #pragma unroll
        for (int c = 0; c < NCH; c++) {
            // ---- build A fragments from the smem stage (LDS.64 x8) ----
            uint32_t ah[2][4], al[2][4];
            if (MODE == 0 && c == 8) {
                #pragma unroll
                for (int mf = 0; mf < 2; mf++) {
                    #pragma unroll
                    for (int h = 0; h < 2; h++) {
                        float2 v;   // cols 128+2tq, 129+2tq
                        v.x = (tq == 0) ? dxr[mf][h] : (tq == 1) ? dzr[mf][h] : 0.f;
                        v.y = (tq == 0) ? dyr[mf][h] : 0.f;
                        split2(v, ah[mf][h], al[mf][h]);
                    }
                    ah[mf][2] = 0u; al[mf][2] = 0u;   // cols >= 136: zero
                    ah[mf][3] = 0u; al[mf][3] = 0u;
                }
            } else {
                float2 ba0, bc0, ba8, bc8;
                if (MODE != 0) {
                    ba0 = *(const float2*)&s_bna[c*16 + 2*tq];
                    bc0 = *(const float2*)&s_bnc[c*16 + 2*tq];
                    ba8 = *(const float2*)&s_bna[c*16 + 2*tq + 8];
                    bc8 = *(const float2*)&s_bnc[c*16 + 2*tq + 8];
                }
                #pragma unroll
                for (int mf = 0; mf < 2; mf++)
                    #pragma unroll
                    for (int h = 0; h < 2; h++) {
                        float2 v0 = *(const float2*)(arow[mf][h] + c*16);
                        float2 v8 = *(const float2*)(arow[mf][h] + c*16 + 8);
                        if (MODE != 0) {
                            v0.x = fmaxf(fmaf(v0.x, ba0.x, bc0.x), 0.f);
                            v0.y = fmaxf(fmaf(v0.y, ba0.y, bc0.y), 0.f);
                            v8.x = fmaxf(fmaf(v8.x, ba8.x, bc8.x), 0.f);
                            v8.y = fmaxf(fmaf(v8.y, ba8.y, bc8.y), 0.f);
                        }
                        split2(v0, ah[mf][h],     al[mf][h]);      // reg h   (k0)
                        split2(v8, ah[mf][2 + h], al[mf][2 + h]);  // reg 2+h (k8)
                    }
            }

            // ---- B fragments from smem ----
            uint32_t bh[8][2], bl[8][2];
            #pragma unroll
            for (int j = 0; j < 4; j++) {
                uint32_t r4[4];
                ldm_x4(r4, wsm_a + (uint32_t)(2*c)*SEGB + boff + j*512);
                bh[2*j][0] = r4[0]; bh[2*j][1] = r4[1];
                bh[2*j+1][0] = r4[2]; bh[2*j+1][1] = r4[3];
                ldm_x4(r4, wsm_a + (uint32_t)(2*c+1)*SEGB + boff + j*512);
                bl[2*j][0] = r4[0]; bl[2*j][1] = r4[1];
                bl[2*j+1][0] = r4[2]; bl[2*j+1][1] = r4[3];
            }
            #pragma unroll
            for (int nf = 0; nf < 8; nf++) {
                mma16816(acc[0][nf], ah[0], bh[nf][0], bh[nf][1]);
                mma16816(acc[1][nf], ah[1], bh[nf][0], bh[nf][1]);
                mma16816(acc[0][nf], ah[0], bl[nf][0], bl[nf][1]);
                mma16816(acc[1][nf], ah[1], bl[nf][0], bl[nf][1]);
                mma16816(acc[0][nf], al[0], bh[nf][0], bh[nf][1]);
                mma16816(acc[1][nf], al[1], bh[nf][0], bh[nf][1]);
            }
        }

        // ---- epilogue: bias, Y write, per-warp stats/max (no barriers) ----
        float bs[8][2];
        #pragma unroll
        for (int nf = 0; nf < 8; nf++) {
            int col = wn*64 + nf*8 + 2*tq;
            bs[nf][0] = s_bias[col];
            bs[nf][1] = s_bias[col+1];
        }
        float s16[8][2], q16[8][2], m16[8][2];
        #pragma unroll
        for (int nf = 0; nf < 8; nf++)
            #pragma unroll
            for (int e = 0; e < 2; e++) { s16[nf][e]=0.f; q16[nf][e]=0.f; m16[nf][e]=-3.4e38f; }

        #pragma unroll
        for (int mf = 0; mf < 2; mf++) {
            #pragma unroll
            for (int nf = 0; nf < 8; nf++) {
                float v0 = acc[mf][nf][0] + bs[nf][0];
                float v1 = acc[mf][nf][1] + bs[nf][1];
                float v2 = acc[mf][nf][2] + bs[nf][0];
                float v3 = acc[mf][nf][3] + bs[nf][1];
                s16[nf][0] += v0 + v2;  s16[nf][1] += v1 + v3;
                q16[nf][0] = fmaf(v0,v0,fmaf(v2,v2,q16[nf][0]));
                q16[nf][1] = fmaf(v1,v1,fmaf(v3,v3,q16[nf][1]));
                m16[nf][0] = fmaxf(m16[nf][0], fmaxf(v0, v2));
                m16[nf][1] = fmaxf(m16[nf][1], fmaxf(v1, v3));
                if (MODE != 2) {
                    int r0 = t*128 + wm*32 + mf*16 + gg;
                    int cb = colTile + wn*64 + nf*8 + 2*tq;
                    *(float2*)(Y + (size_t)r0*COUTT + cb)     = make_float2(v0, v1);
                    *(float2*)(Y + (size_t)(r0+8)*COUTT + cb) = make_float2(v2, v3);
                }
            }
        }

        #pragma unroll
        for (int off = 4; off <= 16; off <<= 1) {
            #pragma unroll
            for (int nf = 0; nf < 8; nf++)
                #pragma unroll
                for (int e = 0; e < 2; e++) {
                    s16[nf][e] += __shfl_xor_sync(0xffffffffu, s16[nf][e], off);
                    q16[nf][e] += __shfl_xor_sync(0xffffffffu, q16[nf][e], off);
                    m16[nf][e] = fmaxf(m16[nf][e], __shfl_xor_sync(0xffffffffu, m16[nf][e], off));
                }
        }
        if (gg == 0) {
            size_t pb = (size_t)(t*4 + wm) * (2*COUTT);
            #pragma unroll
            for (int nf = 0; nf < 8; nf++)
                #pragma unroll
                for (int e = 0; e < 2; e++) {
                    int cl = wn*64 + nf*8 + 2*tq + e;
                    g_part[pb + colTile + cl]         = s16[nf][e];
                    g_part[pb + COUTT + colTile + cl] = q16[nf][e];
                    if (MODE == 2)
                        g_gmax[((size_t)(t*4 + wm))*COUT3 + colTile + cl] = m16[nf][e];
                }
        }

        // ---- stage t+1 arrived (mine) + pair sibling done with this buffer
        CP_WAIT0();
        BAR_PAIR(wm + 1);
        buf ^= 1;
    }
}

// ---------------------------------------------------------------------------
// BN finalize: fixed-order reduce over 4*NBLK per-warp partials
// ---------------------------------------------------------------------------
__global__ void bn_finalize_kernel(int C,
                                   const float* __restrict__ g,
                                   const float* __restrict__ beta,
                                   float* __restrict__ bn_a,
                                   float* __restrict__ bn_c) {
    __shared__ float sh_s[256], sh_q[256];
    int ch = blockIdx.x;
    int t  = threadIdx.x;
    float s = 0.f, q = 0.f;
    for (int b = t; b < 4*NBLK; b += 256) {
        size_t base = (size_t)b * (2*C);
        s += g_part[base + ch];
        q += g_part[base + C + ch];
    }
    sh_s[t] = s; sh_q[t] = q;
    __syncthreads();
    for (int off = 128; off > 0; off >>= 1) {
        if (t < off) { sh_s[t] += sh_s[t+off]; sh_q[t] += sh_q[t+off]; }
        __syncthreads();
    }
    if (t == 0) {
        const float invR = 1.0f / (float)RROWS;
        float mu  = sh_s[0] * invR;
        float var = sh_q[0] * invR - mu*mu;
        float a = g[ch] * rsqrtf(var + 1e-5f);
        bn_a[ch] = a;
        bn_c[ch] = beta[ch] - a*mu;
    }
}

// ---------------------------------------------------------------------------
// Final: relu(a3*gmax + c3) -> out (a3>0 so BN+relu commute with max)
// ---------------------------------------------------------------------------
__global__ void final_out_kernel(const float* __restrict__ bn_a,
                                 const float* __restrict__ bn_c,
                                 float* __restrict__ out) {
    int grp = blockIdx.x;
    int co  = threadIdx.x;
    float v = g_gmax[(size_t)grp*COUT3 + co];
    float r = fmaxf(fmaf(bn_a[co], v, bn_c[co]), 0.f);
    int b = grp >> 10, m = grp & 1023;
    out[OUT_XYZ_ELEMS + ((size_t)(b*COUT3 + co))*MM + m] = r;
}

// ---------------------------------------------------------------------------
// host launcher (gemm_rr<0> stays at launch index 3 for the ncu window)
// ---------------------------------------------------------------------------
extern "C" void kernel_launch(void* const* d_in, const int* in_sizes, int n_in,
                              void* d_out, int out_size) {
    const float* xyz     = (const float*)d_in[0];
    const float* feat    = (const float*)d_in[1];
    const int*   indices = (const int*)  d_in[2];
    const float* w1 = (const float*)d_in[3];
    const float* b1 = (const float*)d_in[4];
    const float* g1 = (const float*)d_in[5];
    const float* e1 = (const float*)d_in[6];
    const float* w2 = (const float*)d_in[7];
    const float* b2 = (const float*)d_in[8];
    const float* g2 = (const float*)d_in[9];
    const float* e2 = (const float*)d_in[10];
    const float* w3 = (const float*)d_in[11];
    const float* b3 = (const float*)d_in[12];
    const float* g3 = (const float*)d_in[13];
    const float* e3 = (const float*)d_in[14];
    float* out = (float*)d_out;

    float *Y1, *Y2, *bn;
    unsigned char *w1s, *w2s, *w3s;
    cudaGetSymbolAddress((void**)&Y1,  g_Y1);
    cudaGetSymbolAddress((void**)&Y2,  g_Y2);
    cudaGetSymbolAddress((void**)&bn,  g_bn);
    cudaGetSymbolAddress((void**)&w1s, g_w1s);
    cudaGetSymbolAddress((void**)&w2s, g_w2s);
    cudaGetSymbolAddress((void**)&w3s, g_w3s);
    float* a1 = bn;            float* c1 = bn + COUT3;
    float* a2 = bn + 2*COUT3;  float* c2 = bn + 3*COUT3;
    float* a3 = bn + 4*COUT3;  float* c3 = bn + 5*COUT3;

    int stageB = 2 * STAGEF * 4;              // 139264
    int smem1  = 18*SEGB + stageB;            // 212992
    int smem23 = 16*SEGB + stageB;            // 204800
    cudaFuncSetAttribute(gemm_rr<0>, cudaFuncAttributeMaxDynamicSharedMemorySize, smem1);
    cudaFuncSetAttribute(gemm_rr<1>, cudaFuncAttributeMaxDynamicSharedMemorySize, smem23);
    cudaFuncSetAttribute(gemm_rr<2>, cudaFuncAttributeMaxDynamicSharedMemorySize, smem23);

    // index 0..2: prep needed by gemm0
    splitw_kernel<<<COUT1, 144>>>(w1, w1s, 131, 18, 1);                     // 0
    {
        dim3 blk(32, 8);
        dim3 grd(NN/128, CC/32, BB);
        transpose_feat_kernel<<<grd, blk>>>(feat);                          // 1
    }
    ballquery_kernel<<<(BB*MM*32)/256, 256>>>(xyz, indices, out);           // 2

    // index 3: layer 1 GEMM (profiling target)
    gemm_rr<0><<<dim3(148,1), 256, smem1>>>(nullptr, w1s, b1, nullptr, nullptr,
                                            Y1, xyz, out);                  // 3
    bn_finalize_kernel<<<COUT1, 256>>>(COUT1, g1, e1, a1, c1);              // 4

    splitw_kernel<<<COUT2, 128>>>(w2, w2s, 128, 16, 0);                     // 5
    gemm_rr<1><<<dim3(148,1), 256, smem23>>>(Y1, w2s, b2, a1, c1,
                                             Y2, nullptr, nullptr);         // 6
    bn_finalize_kernel<<<COUT2, 256>>>(COUT2, g2, e2, a2, c2);              // 7

    splitw_kernel<<<COUT3, 128>>>(w3, w3s, 128, 16, 0);                     // 8
    gemm_rr<2><<<dim3(74,2), 256, smem23>>>(Y2, w3s, b3, a2, c2,
                                            nullptr, nullptr, nullptr);     // 9
    bn_finalize_kernel<<<COUT3, 256>>>(COUT3, g3, e3, a3, c3);              // 10

    final_out_kernel<<<NGRP, COUT3>>>(a3, c3, out);                         // 11
}